// round 12
// baseline (speedup 1.0000x reference)
#include <cuda_runtime.h>

// EMD approx-match (auction annealing), B=8, N=M=2048, 3-D points.
// R11: 32-point chunk AABBs (64/cloud) + warp-uniform box-box chunk tests
// inside the pair loops -> skip LDS+FMA for underflowed 32-column chunks.
// (R10's 256-pt segment boxes were too coarse to ever fire.)
// Persistent kernel, __noinline__ phases, per-batch reset-free barriers.

#define BB 8
#define NN 2048
#define MM 2048
#define EPSF 1e-9f
#define LOG2E 1.4426950408889634f
#define TMIN -126.0f

#define NT   1024
#define RPC  128
#define SEGS 8
#define SEGL 256
#define NCH  64          // 32-point chunks per cloud

// dynamic shared memory layout
#define SM_TILE    0        // float4[2048] 32768  (sort reuses as u64[2048])
#define SM_TILE2   32768    // float[2048]   8192
#define SM_RED     40960    // float[1024]   4096
#define SM_CWARP   45056    // float[32]      128
#define SM_WMAX1   45184    // float[64]      256
#define SM_WMAX2   45440    // float[64]      256
#define SM_SLS     45696
#define SM_TOTAL   45760

__device__ float4 g_p1[BB * NN], g_p2[BB * MM];       // sorted (x,y,z,|p|^2)
__device__ float4 g_c1lo[BB * NCH], g_c1hi[BB * NCH]; // 32-pt chunk boxes
__device__ float4 g_c2lo[BB * NCH], g_c2hi[BB * NCH];
__device__ float g_s [BB * NN];
__device__ float g_ss[BB * MM];
__device__ float g_rL[2][BB * NN];
__device__ float g_rR[2][BB * MM];
__device__ unsigned g_barb[BB];

__constant__ float c_lv[10] = {
    -16384.f, -4096.f, -1024.f, -256.f, -64.f, -16.f, -4.f, -1.f, -0.25f, 0.f
};

__device__ __forceinline__ float lg2f(float x) {
    float r; asm("lg2.approx.f32 %0, %1;" : "=f"(r) : "f"(x)); return r;
}
__device__ __forceinline__ float ex2f(float x) {
    float r; asm("ex2.approx.f32 %0, %1;" : "=f"(r) : "f"(x)); return r;
}
__device__ __forceinline__ float sqrt_apx(float x) {
    float r; asm("sqrt.approx.f32 %0, %1;" : "=f"(r) : "f"(x)); return r;
}
__device__ __forceinline__ unsigned expand10(unsigned v) {
    v &= 1023u;
    v = (v | (v << 16)) & 0x030000FFu;
    v = (v | (v << 8))  & 0x0300F00Fu;
    v = (v | (v << 4))  & 0x030C30C3u;
    v = (v | (v << 2))  & 0x09249249u;
    return v;
}
// min squared distance between two AABBs (0 if overlapping)
__device__ __forceinline__ float boxbox(float4 lo1, float4 hi1,
                                        float4 lo2, float4 hi2) {
    float dx = fmaxf(fmaxf(lo2.x - hi1.x, lo1.x - hi2.x), 0.f);
    float dy = fmaxf(fmaxf(lo2.y - hi1.y, lo1.y - hi2.y), 0.f);
    float dz = fmaxf(fmaxf(lo2.z - hi1.z, lo1.z - hi2.z), 0.f);
    return fmaf(dx, dx, fmaf(dy, dy, dz * dz));
}

// Per-batch reset-free barrier (16 CTAs). Counter is monotonic; every kernel
// execution adds a multiple of 16, so (arr & ~15)+16 is always the right
// release target, across phases and graph replays.
__device__ __forceinline__ void batch_sync(int b) {
    __syncthreads();
    if (threadIdx.x == 0) {
        __threadfence();
        unsigned arr = atomicAdd(&g_barb[b], 1u);
        unsigned target = (arr & ~15u) + 16u;
        unsigned curv;
        do {
            __nanosleep(32);
            asm volatile("ld.global.cv.u32 %0, [%1];" : "=r"(curv) : "l"(&g_barb[b]));
        } while ((int)(curv - target) < 0);
        __threadfence();
    }
    __syncthreads();
}

// ---------------- phase -1: Morton sort + chunk boxes + init ----------------
__device__ __noinline__ void phase_sort(const float* __restrict__ x1,
                                        const float* __restrict__ x2,
                                        float* __restrict__ out) {
    extern __shared__ char smem[];
    unsigned long long* keys = (unsigned long long*)(smem + SM_TILE);
    const int b = blockIdx.y, bx = blockIdx.x, tid = threadIdx.x;
    const int lane = tid & 31, wid = tid >> 5;

    if (bx < 2) {
        const float* src = (bx == 0) ? x1 + (size_t)b * NN * 3
                                     : x2 + (size_t)b * MM * 3;
        float4* dst = (bx == 0) ? g_p1 + b * NN : g_p2 + b * MM;

        for (int j = tid; j < NN; j += NT) {
            float x = src[j * 3], y = src[j * 3 + 1], z = src[j * 3 + 2];
            unsigned ux = (unsigned)(int)fminf(fmaxf((x + 5.f) * 102.4f, 0.f), 1023.f);
            unsigned uy = (unsigned)(int)fminf(fmaxf((y + 5.f) * 102.4f, 0.f), 1023.f);
            unsigned uz = (unsigned)(int)fminf(fmaxf((z + 5.f) * 102.4f, 0.f), 1023.f);
            unsigned code = (expand10(ux) << 2) | (expand10(uy) << 1) | expand10(uz);
            keys[j] = ((unsigned long long)code << 11) | (unsigned)j;
        }
        __syncthreads();
        for (int k = 2; k <= NN; k <<= 1) {
            for (int jj = k >> 1; jj > 0; jj >>= 1) {
                for (int i2 = tid; i2 < NN; i2 += NT) {
                    int ixj = i2 ^ jj;
                    if (ixj > i2) {
                        bool up = ((i2 & k) == 0);
                        unsigned long long a = keys[i2], bb = keys[ixj];
                        if ((a > bb) == up) { keys[i2] = bb; keys[ixj] = a; }
                    }
                }
                __syncthreads();
            }
        }
        for (int j = tid; j < NN; j += NT) {
            int idx = (int)(keys[j] & 2047ull);
            float x = src[idx * 3], y = src[idx * 3 + 1], z = src[idx * 3 + 2];
            dst[j] = make_float4(x, y, z, fmaf(x, x, fmaf(y, y, z * z)));
        }
        __syncthreads();
        // 32-point chunk AABBs: warp w handles chunks w, w+32
        float4* blo = (bx == 0) ? g_c1lo : g_c2lo;
        float4* bhi = (bx == 0) ? g_c1hi : g_c2hi;
        for (int c = wid; c < NCH; c += 32) {
            float4 p = dst[c * 32 + lane];
            float lx = p.x, ly = p.y, lz = p.z;
            float hx = p.x, hy = p.y, hz = p.z;
#pragma unroll
            for (int off = 16; off; off >>= 1) {
                lx = fminf(lx, __shfl_xor_sync(0xffffffffu, lx, off));
                ly = fminf(ly, __shfl_xor_sync(0xffffffffu, ly, off));
                lz = fminf(lz, __shfl_xor_sync(0xffffffffu, lz, off));
                hx = fmaxf(hx, __shfl_xor_sync(0xffffffffu, hx, off));
                hy = fmaxf(hy, __shfl_xor_sync(0xffffffffu, hy, off));
                hz = fmaxf(hz, __shfl_xor_sync(0xffffffffu, hz, off));
            }
            if (lane == 0) {
                blo[b * NCH + c] = make_float4(lx, ly, lz, 0.f);
                bhi[b * NCH + c] = make_float4(hx, hy, hz, 0.f);
            }
        }
    } else if (bx == 2) {
        for (int j = tid; j < NN; j += NT) g_rL[0][b * NN + j] = 1.0f;
    } else if (bx == 3) {
        for (int j = tid; j < MM; j += NT) g_rR[0][b * MM + j] = 1.0f;
    } else if (bx == 4 && tid == 0) {
        out[b] = 0.0f;
    }
}

// ---------------- phase 0: rowsum(level 0), rR==1 ----------------
__device__ __noinline__ void phase0() {
    extern __shared__ char smem[];
    float4* tile = (float4*)(smem + SM_TILE);
    float*  red  = (float*)(smem + SM_RED);
    const int b = blockIdx.y, bx = blockIdx.x, tid = threadIdx.x;
    const int r = bx * RPC + (tid & (RPC - 1));
    const int m0 = (tid >> 7) * SEGL;
    const int ch0 = m0 >> 5;                       // first col-chunk
    const int rowch = bx * 4 + ((tid >> 5) & 3);   // warp's 32-row chunk
    const float q = c_lv[0] * LOG2E;
    const float n2q = -2.0f * q;

    for (int j = tid; j < MM; j += NT) {
        float4 p = g_p2[b * MM + j];
        tile[j] = make_float4(n2q * p.x, n2q * p.y, n2q * p.z, q * p.w);
    }
    __syncthreads();
    float4 X = g_p1[b * NN + r];
    float a = q * X.w;
    float4 rlo = g_c1lo[b * NCH + rowch], rhi = g_c1hi[b * NCH + rowch];

    float s0 = 0.f, s1 = 0.f;
    for (int ch = 0; ch < 8; ch++) {
        float dlb = boxbox(rlo, rhi, g_c2lo[b * NCH + ch0 + ch],
                                     g_c2hi[b * NCH + ch0 + ch]);
        if (dlb * q <= TMIN) continue;             // warp-uniform skip
        int mb = m0 + ch * 32;
#pragma unroll 2
        for (int m = mb; m < mb + 32; m += 4) {
            float4 P0 = tile[m], P1 = tile[m + 1], P2 = tile[m + 2], P3 = tile[m + 3];
            float t0 = fmaf(X.x, P0.x, fmaf(X.y, P0.y, fmaf(X.z, P0.z, a + P0.w)));
            float t1 = fmaf(X.x, P1.x, fmaf(X.y, P1.y, fmaf(X.z, P1.z, a + P1.w)));
            float t2 = fmaf(X.x, P2.x, fmaf(X.y, P2.y, fmaf(X.z, P2.z, a + P2.w)));
            float t3 = fmaf(X.x, P3.x, fmaf(X.y, P3.y, fmaf(X.z, P3.z, a + P3.w)));
            float tm = fmaxf(fmaxf(t0, t1), fmaxf(t2, t3));
            if (__ballot_sync(0xffffffffu, tm > TMIN) != 0u) {
                s0 += ex2f(t0) + ex2f(t2);
                s1 += ex2f(t1) + ex2f(t3);
            }
        }
    }
    red[tid] = s0 + s1;
    __syncthreads();
    if (tid < RPC) {
        float v = 0.f;
#pragma unroll
        for (int k = 0; k < SEGS; k++) v += red[tid + (k << 7)];
        g_s[b * NN + bx * RPC + tid] = v;
    }
}

// ---------------- colsum: ss[b][m] ----------------
// T: 0 = dense, 2 = chunk box tests + group ballots
template <int T>
__device__ __noinline__ void phase_colsum(int cur, float q) {
    extern __shared__ char smem[];
    float4* tile  = (float4*)(smem + SM_TILE);
    float*  red   = (float*)(smem + SM_RED);
    float*  wmax1 = (float*)(smem + SM_WMAX1);
    const int b = blockIdx.y, bx = blockIdx.x, tid = threadIdx.x;
    const int mcol = bx * RPC + (tid & (RPC - 1));
    const int n0 = (tid >> 7) * SEGL;
    const int ch0 = n0 >> 5;
    const int colch = bx * 4 + ((tid >> 5) & 3);   // warp's 32-col chunk (cloud2)
    const float n2q = -2.0f * q;

    for (int j = tid; j < NN; j += NT) {
        float4 p = g_p1[b * NN + j];
        float rl = g_rL[cur][b * NN + j];
        float sv = g_s[b * NN + j];
        float lr = lg2f(__fdividef(rl, sv + EPSF));
        tile[j] = make_float4(n2q * p.x, n2q * p.y, n2q * p.z, fmaf(q, p.w, lr));
        if (T >= 2) {
            float mx = lr;
#pragma unroll
            for (int off = 16; off; off >>= 1)
                mx = fmaxf(mx, __shfl_xor_sync(0xffffffffu, mx, off));
            if ((tid & 31) == 0) wmax1[j >> 5] = mx;
        }
    }
    __syncthreads();

    float4 Y = g_p2[b * MM + mcol];
    float lrm = lg2f(g_rR[cur][b * MM + mcol]);
    float c = fmaf(q, Y.w, lrm);
    float4 clo, chi;
    if (T >= 2) {
        clo = g_c2lo[b * NCH + colch];
        chi = g_c2hi[b * NCH + colch];
    }

    float s0 = 0.f, s1 = 0.f;
    for (int ch = 0; ch < 8; ch++) {
        if (T >= 2) {
            float dlb = boxbox(clo, chi, g_c1lo[b * NCH + ch0 + ch],
                                         g_c1hi[b * NCH + ch0 + ch]);
            float bnd = fmaf(dlb, q, wmax1[ch0 + ch] + lrm);
            if (__ballot_sync(0xffffffffu, bnd > TMIN) == 0u) continue;
        }
        int nb = n0 + ch * 32;
#pragma unroll 2
        for (int n = nb; n < nb + 32; n += 4) {
            float4 P0 = tile[n], P1 = tile[n + 1], P2 = tile[n + 2], P3 = tile[n + 3];
            float t0 = fmaf(Y.x, P0.x, fmaf(Y.y, P0.y, fmaf(Y.z, P0.z, c + P0.w)));
            float t1 = fmaf(Y.x, P1.x, fmaf(Y.y, P1.y, fmaf(Y.z, P1.z, c + P1.w)));
            float t2 = fmaf(Y.x, P2.x, fmaf(Y.y, P2.y, fmaf(Y.z, P2.z, c + P2.w)));
            float t3 = fmaf(Y.x, P3.x, fmaf(Y.y, P3.y, fmaf(Y.z, P3.z, c + P3.w)));
            bool go = true;
            if (T >= 1) {
                float tm = fmaxf(fmaxf(t0, t1), fmaxf(t2, t3));
                go = __ballot_sync(0xffffffffu, tm > TMIN) != 0u;
            }
            if (go) {
                s0 += ex2f(t0) + ex2f(t2);
                s1 += ex2f(t1) + ex2f(t3);
            }
        }
    }
    red[tid] = s0 + s1;
    __syncthreads();
    if (tid < RPC) {
        float v = 0.f;
#pragma unroll
        for (int k = 0; k < SEGS; k++) v += red[tid + (k << 7)];
        g_ss[b * MM + bx * RPC + tid] = v;
    }
}

// ---------------- fused: pass3(level i) + rowsum(level i+1) ----------------
template <int T1, int T2>
__device__ __noinline__ void phase_fused(int cur, float q, float q2,
                                         float* __restrict__ out) {
    extern __shared__ char smem[];
    float4* tile  = (float4*)(smem + SM_TILE);
    float*  tile2 = (float*)(smem + SM_TILE2);
    float*  red   = (float*)(smem + SM_RED);
    float*  cwarp = (float*)(smem + SM_CWARP);
    float*  wmax1 = (float*)(smem + SM_WMAX1);
    float*  wmax2 = (float*)(smem + SM_WMAX2);
    const int b = blockIdx.y, bx = blockIdx.x, tid = threadIdx.x;
    const int lane = tid & 31, wid = tid >> 5;
    const int r  = bx * RPC + (tid & (RPC - 1));
    const int m0 = (tid >> 7) * SEGL;
    const int ch0 = m0 >> 5;
    const int rowch = bx * 4 + (wid & 3);
    const int rown = b * NN + bx * RPC + tid;

    for (int j = tid; j < MM; j += NT) {
        float4 p = g_p2[b * MM + j];
        float rr  = g_rR[cur][b * MM + j];
        float ssv = g_ss[b * MM + j];
        float ratio = fminf(__fdividef(rr, ssv + EPSF), 1.0f);
        float lr1 = lg2f(rr * ratio);
        tile[j] = make_float4(p.x, p.y, p.z, lr1);
        float rrn = fmaxf(rr - ratio * ssv, 0.0f);
        float lr2 = lg2f(rrn);
        tile2[j] = lr2;
        if (bx == 0) g_rR[cur ^ 1][b * MM + j] = rrn;   // exact identity
        if (T1 >= 2) {
            float mx = lr1;
#pragma unroll
            for (int off = 16; off; off >>= 1)
                mx = fmaxf(mx, __shfl_xor_sync(0xffffffffu, mx, off));
            if ((tid & 31) == 0) wmax1[j >> 5] = mx;
        }
        if (T2 >= 2) {
            float mx = lr2;
#pragma unroll
            for (int off = 16; off; off >>= 1)
                mx = fmaxf(mx, __shfl_xor_sync(0xffffffffu, mx, off));
            if ((tid & 31) == 0) wmax2[j >> 5] = mx;
        }
    }
    __syncthreads();

    float4 X = g_p1[b * NN + r];
    float rl = g_rL[cur][b * NN + r];
    float sv = g_s[b * NN + r];
    float F  = __fdividef(rl, sv + EPSF);
    float4 rlo, rhi;
    if (T1 >= 2 || T2 >= 2) {
        rlo = g_c1lo[b * NCH + rowch];
        rhi = g_c1hi[b * NCH + rowch];
    }

    float rs0 = 0.f, rs1 = 0.f, c0 = 0.f, c1 = 0.f, sn0 = 0.f, sn1 = 0.f;
    const float4* t2v = (const float4*)tile2;
    for (int ch = 0; ch < 8; ch++) {
        bool aT = true, aU = true;
        if (T1 >= 2 || T2 >= 2) {
            float dlb = boxbox(rlo, rhi, g_c2lo[b * NCH + ch0 + ch],
                                         g_c2hi[b * NCH + ch0 + ch]);
            if (T1 >= 2) aT = fmaf(dlb, q,  wmax1[ch0 + ch]) > TMIN;  // warp-uniform
            if (T2 >= 2) aU = fmaf(dlb, q2, wmax2[ch0 + ch]) > TMIN;
            if (!aT && !aU) continue;
        }
        int mb = m0 + ch * 32;
        for (int m = mb; m < mb + 32; m += 4) {
            float4 P0 = tile[m], P1 = tile[m + 1], P2 = tile[m + 2], P3 = tile[m + 3];
            float dx0 = X.x - P0.x, dy0 = X.y - P0.y, dz0 = X.z - P0.z;
            float dx1 = X.x - P1.x, dy1 = X.y - P1.y, dz1 = X.z - P1.z;
            float dx2 = X.x - P2.x, dy2 = X.y - P2.y, dz2 = X.z - P2.z;
            float dx3 = X.x - P3.x, dy3 = X.y - P3.y, dz3 = X.z - P3.z;
            float d20 = fmaf(dx0, dx0, fmaf(dy0, dy0, dz0 * dz0));
            float d21 = fmaf(dx1, dx1, fmaf(dy1, dy1, dz1 * dz1));
            float d22 = fmaf(dx2, dx2, fmaf(dy2, dy2, dz2 * dz2));
            float d23 = fmaf(dx3, dx3, fmaf(dy3, dy3, dz3 * dz3));
            if (aT) {
                float t0 = fmaf(d20, q, P0.w);
                float t1 = fmaf(d21, q, P1.w);
                float t2 = fmaf(d22, q, P2.w);
                float t3 = fmaf(d23, q, P3.w);
                bool go1 = true;
                if (T1 >= 1) {
                    float tm = fmaxf(fmaxf(t0, t1), fmaxf(t2, t3));
                    go1 = __ballot_sync(0xffffffffu, tm > TMIN) != 0u;
                }
                if (go1) {
                    float w0 = ex2f(t0), w1 = ex2f(t1), w2 = ex2f(t2), w3 = ex2f(t3);
                    rs0 += w0 + w2; rs1 += w1 + w3;
                    c0 = fmaf(w0, sqrt_apx(d20), c0);
                    c1 = fmaf(w1, sqrt_apx(d21), c1);
                    c0 = fmaf(w2, sqrt_apx(d22), c0);
                    c1 = fmaf(w3, sqrt_apx(d23), c1);
                }
            }
            if (aU) {
                float4 T = t2v[m >> 2];
                float u0 = fmaf(d20, q2, T.x);
                float u1 = fmaf(d21, q2, T.y);
                float u2 = fmaf(d22, q2, T.z);
                float u3 = fmaf(d23, q2, T.w);
                bool go2 = true;
                if (T2 >= 1) {
                    float um = fmaxf(fmaxf(u0, u1), fmaxf(u2, u3));
                    go2 = __ballot_sync(0xffffffffu, um > TMIN) != 0u;
                }
                if (go2) {
                    sn0 += ex2f(u0) + ex2f(u2);
                    sn1 += ex2f(u1) + ex2f(u3);
                }
            }
        }
    }

    float c = (c0 + c1) * F;
#pragma unroll
    for (int off = 16; off > 0; off >>= 1)
        c += __shfl_down_sync(0xffffffffu, c, off);
    if (lane == 0) cwarp[wid] = c;

    red[tid] = rs0 + rs1;
    __syncthreads();
    if (tid < RPC) {
        float v = 0.f;
#pragma unroll
        for (int k = 0; k < SEGS; k++) v += red[tid + (k << 7)];
        g_rL[cur ^ 1][rown] = fmaxf(rl - v * F, 0.0f);   // tid<RPC owns row r
    }
    __syncthreads();
    red[tid] = sn0 + sn1;
    __syncthreads();
    if (tid < RPC) {
        float v = 0.f;
#pragma unroll
        for (int k = 0; k < SEGS; k++) v += red[tid + (k << 7)];
        g_s[rown] = v;                                   // rowsum level i+1
    }
    if (wid == 0) {
        float v = cwarp[lane];
#pragma unroll
        for (int off = 16; off > 0; off >>= 1)
            v += __shfl_down_sync(0xffffffffu, v, off);
        if (lane == 0) atomicAdd(&out[b], v);
    }
}

// ---------------- level 9 (L=0): analytic s/ss, one cost pass ----------------
__device__ __noinline__ void phase_last(int cur, float* __restrict__ out) {
    extern __shared__ char smem[];
    float4* tile  = (float4*)(smem + SM_TILE);
    float*  red   = (float*)(smem + SM_RED);
    float*  cwarp = (float*)(smem + SM_CWARP);
    float*  SLs   = (float*)(smem + SM_SLS);
    const int b = blockIdx.y, bx = blockIdx.x, tid = threadIdx.x;
    const int lane = tid & 31, wid = tid >> 5;
    const int r  = bx * RPC + (tid & (RPC - 1));
    const int m0 = (tid >> 7) * SEGL;

    const float* rR = g_rR[cur] + b * MM;
    const float* rL = g_rL[cur] + b * NN;
    const float* sp = g_s + b * NN;   // s[n] = sum rR (from fused(8), q2=0)

    float acc = 0.f;
    for (int j = tid; j < NN; j += NT)
        acc += __fdividef(rL[j], sp[j] + EPSF);
    red[tid] = acc;
    __syncthreads();
    if (tid < 32) {
        float v = 0.f;
#pragma unroll
        for (int k = 0; k < NT / 32; k++) v += red[tid + k * 32];
#pragma unroll
        for (int off = 16; off > 0; off >>= 1)
            v += __shfl_down_sync(0xffffffffu, v, off);
        if (tid == 0) *SLs = v;
    }
    __syncthreads();
    const float SL = *SLs;

    for (int j = tid; j < MM; j += NT) {
        float4 p = g_p2[b * MM + j];
        float rr = rR[j];
        float ratio = fminf(__fdividef(rr, fmaf(rr, SL, EPSF)), 1.0f);
        tile[j] = make_float4(p.x, p.y, p.z, rr * ratio);
    }
    __syncthreads();

    float4 X = g_p1[b * NN + r];
    float F = __fdividef(rL[r], sp[r] + EPSF);
    float c0 = 0.f, c1 = 0.f;
#pragma unroll 2
    for (int m = m0; m < m0 + SEGL; m += 2) {
        float4 P0 = tile[m], P1 = tile[m + 1];
        float dx0 = X.x - P0.x, dy0 = X.y - P0.y, dz0 = X.z - P0.z;
        float dx1 = X.x - P1.x, dy1 = X.y - P1.y, dz1 = X.z - P1.z;
        float d20 = fmaf(dx0, dx0, fmaf(dy0, dy0, dz0 * dz0));
        float d21 = fmaf(dx1, dx1, fmaf(dy1, dy1, dz1 * dz1));
        c0 = fmaf(P0.w, sqrt_apx(d20), c0);
        c1 = fmaf(P1.w, sqrt_apx(d21), c1);
    }
    float c = (c0 + c1) * F;
#pragma unroll
    for (int off = 16; off > 0; off >>= 1)
        c += __shfl_down_sync(0xffffffffu, c, off);
    if (lane == 0) cwarp[wid] = c;
    __syncthreads();
    if (wid == 0) {
        float v = cwarp[lane];
#pragma unroll
        for (int off = 16; off > 0; off >>= 1)
            v += __shfl_down_sync(0xffffffffu, v, off);
        if (lane == 0) atomicAdd(&out[b], v);
    }
}

__global__ void __launch_bounds__(NT, 1)
k_emd(const float* __restrict__ x1, const float* __restrict__ x2,
      float* __restrict__ out) {
    const int b = blockIdx.y;

    phase_sort(x1, x2, out);
    batch_sync(b);

    phase0();
    batch_sync(b);

    int cur = 0;
#pragma unroll 1
    for (int i = 0; i < 9; i++) {
        const float q  = c_lv[i] * LOG2E;
        const float q2 = c_lv[i + 1] * LOG2E;

        if (i <= 4) {            // levels -16384 .. -64  (next: .. -16)
            phase_colsum<2>(cur, q);  batch_sync(b);
            phase_fused<2, 2>(cur, q, q2, out);
        } else if (i == 5) {     // level -16 (next: -4, dense)
            phase_colsum<2>(cur, q);  batch_sync(b);
            phase_fused<2, 0>(cur, q, q2, out);
        } else {                 // levels -4, -1, -0.25 (dense)
            phase_colsum<0>(cur, q);  batch_sync(b);
            phase_fused<0, 0>(cur, q, q2, out);
        }
        batch_sync(b);
        cur ^= 1;
    }

    phase_last(cur, out);
}

extern "C" void kernel_launch(void* const* d_in, const int* in_sizes, int n_in,
                              void* d_out, int out_size) {
    const float* x1 = (const float*)d_in[0];
    const float* x2 = (const float*)d_in[1];
    float* out = (float*)d_out;
    dim3 grid(NN / RPC, BB);   // (16, 8) = 128 CTAs, all co-resident (<=148 SMs)
    k_emd<<<grid, NT, SM_TOTAL>>>(x1, x2, out);
}

// round 13
// speedup vs baseline: 1.0575x; 1.0575x over previous
#include <cuda_runtime.h>

// EMD approx-match (auction annealing), B=8, N=M=2048, 3-D points.
// R12: revert to multi-kernel (R4 structure, best-known baseline) and reclaim
// inter-launch gaps with PDL (programmatic dependent launch) instead of
// software barriers. k_init merged into k_rowsum0; single instantiation of
// each kernel (ballots always on) for a small I-footprint.

#define BB 8
#define NN 2048
#define MM 2048
#define EPSF 1e-9f
#define LOG2E 1.4426950408889634f
#define TMIN -126.0f

#define NT   1024
#define RPC  128
#define SEGS 8
#define SEGL (MM / SEGS)   // 256

__device__ float g_s [BB * NN];
__device__ float g_ss[BB * MM];
__device__ float g_rL[2][BB * NN];
__device__ float g_rR[2][BB * MM];

__device__ __forceinline__ float lg2f(float x) {
    float r; asm("lg2.approx.f32 %0, %1;" : "=f"(r) : "f"(x)); return r;
}
__device__ __forceinline__ float ex2f(float x) {
    float r; asm("ex2.approx.f32 %0, %1;" : "=f"(r) : "f"(x)); return r;
}
__device__ __forceinline__ float sqrt_apx(float x) {
    float r; asm("sqrt.approx.f32 %0, %1;" : "=f"(r) : "f"(x)); return r;
}
// PDL device controls
__device__ __forceinline__ void pdl_trigger() {
    asm volatile("griddepcontrol.launch_dependents;");
}
__device__ __forceinline__ void pdl_wait() {
    asm volatile("griddepcontrol.wait;" ::: "memory");
}

// ---------------- rowsum(level 0) + state init (rR==1 -> lg2 term = 0) ----------------
__global__ void __launch_bounds__(NT, 1)
k_rowsum0(const float* __restrict__ x1, const float* __restrict__ x2,
          float* __restrict__ out, float q) {
    __shared__ float4 tile[MM];
    __shared__ float  red[NT];
    pdl_trigger();
    const int b = blockIdx.y, bx = blockIdx.x, tid = threadIdx.x;
    const int r  = bx * RPC + (tid & (RPC - 1));
    const int m0 = (tid >> 7) * SEGL;
    const float n2q = -2.0f * q;

    // init (this kernel has no PSS attr -> fully ordered after prior replay)
    if (tid < RPC) {
        g_rL[0][b * NN + bx * RPC + tid] = 1.0f;
        g_rR[0][b * MM + bx * RPC + tid] = 1.0f;
    }
    if (bx == 0 && tid == 0) out[b] = 0.0f;

    for (int j = tid; j < MM; j += NT) {
        const float* yp = x2 + ((size_t)b * MM + j) * 3;
        float y0 = yp[0], y1 = yp[1], y2 = yp[2];
        float c  = q * fmaf(y0, y0, fmaf(y1, y1, y2 * y2));
        tile[j] = make_float4(n2q * y0, n2q * y1, n2q * y2, c);
    }
    __syncthreads();

    const float* xp = x1 + ((size_t)b * NN + r) * 3;
    float X0 = xp[0], X1 = xp[1], X2 = xp[2];
    float a  = q * fmaf(X0, X0, fmaf(X1, X1, X2 * X2));

    float s0 = 0.f, s1 = 0.f, s2 = 0.f, s3 = 0.f;
#pragma unroll 4
    for (int m = m0; m < m0 + SEGL; m += 4) {
        float4 P0 = tile[m + 0], P1 = tile[m + 1], P2 = tile[m + 2], P3 = tile[m + 3];
        float t0 = fmaf(X0, P0.x, fmaf(X1, P0.y, fmaf(X2, P0.z, a + P0.w)));
        float t1 = fmaf(X0, P1.x, fmaf(X1, P1.y, fmaf(X2, P1.z, a + P1.w)));
        float t2 = fmaf(X0, P2.x, fmaf(X1, P2.y, fmaf(X2, P2.z, a + P2.w)));
        float t3 = fmaf(X0, P3.x, fmaf(X1, P3.y, fmaf(X2, P3.z, a + P3.w)));
        float tm = fmaxf(fmaxf(t0, t1), fmaxf(t2, t3));
        if (__ballot_sync(0xffffffffu, tm > TMIN) != 0u) {
            s0 += ex2f(t0); s1 += ex2f(t1); s2 += ex2f(t2); s3 += ex2f(t3);
        }
    }
    red[tid] = (s0 + s1) + (s2 + s3);
    __syncthreads();
    if (tid < RPC) {
        float v = 0.f;
#pragma unroll
        for (int k = 0; k < SEGS; k++) v += red[tid + (k << 7)];
        g_s[(size_t)b * NN + bx * RPC + tid] = v;
    }
}

// ---------------- colsum: ss[b][m] ----------------
__global__ void __launch_bounds__(NT, 1)
k_colsum(const float* __restrict__ x1, const float* __restrict__ x2,
         int cur, float q) {
    __shared__ float4 tile[NN];
    __shared__ float  red[NT];
    pdl_trigger();
    const int b = blockIdx.y, bx = blockIdx.x, tid = threadIdx.x;
    const int mcol = bx * RPC + (tid & (RPC - 1));
    const int n0 = (tid >> 7) * SEGL;
    const float n2q = -2.0f * q;

    // independent prologue: own column's coords (inputs are read-only)
    const float* yp = x2 + ((size_t)b * MM + mcol) * 3;
    float Y0 = yp[0], Y1 = yp[1], Y2 = yp[2];

    pdl_wait();   // predecessor (fused i-1 / rowsum0) wrote g_rL, g_s, g_rR

    for (int j = tid; j < NN; j += NT) {
        const float* xq = x1 + ((size_t)b * NN + j) * 3;
        float a0 = xq[0], a1 = xq[1], a2 = xq[2];
        float rl = g_rL[cur][b * NN + j];
        float sv = g_s[b * NN + j];
        float f  = __fdividef(rl, sv + EPSF);
        float aj = fmaf(q, fmaf(a0, a0, fmaf(a1, a1, a2 * a2)), lg2f(f));
        tile[j] = make_float4(n2q * a0, n2q * a1, n2q * a2, aj);
    }
    __syncthreads();

    float c = fmaf(q, fmaf(Y0, Y0, fmaf(Y1, Y1, Y2 * Y2)),
                   lg2f(g_rR[cur][b * MM + mcol]));

    float s0 = 0.f, s1 = 0.f, s2 = 0.f, s3 = 0.f;
#pragma unroll 4
    for (int n = n0; n < n0 + SEGL; n += 4) {
        float4 P0 = tile[n + 0], P1 = tile[n + 1], P2 = tile[n + 2], P3 = tile[n + 3];
        float t0 = fmaf(Y0, P0.x, fmaf(Y1, P0.y, fmaf(Y2, P0.z, c + P0.w)));
        float t1 = fmaf(Y0, P1.x, fmaf(Y1, P1.y, fmaf(Y2, P1.z, c + P1.w)));
        float t2 = fmaf(Y0, P2.x, fmaf(Y1, P2.y, fmaf(Y2, P2.z, c + P2.w)));
        float t3 = fmaf(Y0, P3.x, fmaf(Y1, P3.y, fmaf(Y2, P3.z, c + P3.w)));
        float tm = fmaxf(fmaxf(t0, t1), fmaxf(t2, t3));
        if (__ballot_sync(0xffffffffu, tm > TMIN) != 0u) {
            s0 += ex2f(t0); s1 += ex2f(t1); s2 += ex2f(t2); s3 += ex2f(t3);
        }
    }
    red[tid] = (s0 + s1) + (s2 + s3);
    __syncthreads();
    if (tid < RPC) {
        float v = 0.f;
#pragma unroll
        for (int k = 0; k < SEGS; k++) v += red[tid + (k << 7)];
        g_ss[b * MM + bx * RPC + tid] = v;
    }
}

// ---------------- fused: pass3(level i) + rowsum(level i+1) ----------------
__global__ void __launch_bounds__(NT, 1)
k_fused(const float* __restrict__ x1, const float* __restrict__ x2,
        int cur, float q, float q2, float* __restrict__ out) {
    __shared__ float4 tile[MM];
    __shared__ __align__(16) float tile2[MM];
    __shared__ float  red[NT];
    __shared__ float  cwarp[NT / 32];
    pdl_trigger();
    const int b = blockIdx.y, bx = blockIdx.x, tid = threadIdx.x;
    const int lane = tid & 31, wid = tid >> 5;
    const int r  = bx * RPC + (tid & (RPC - 1));
    const int m0 = (tid >> 7) * SEGL;
    const int rown = b * NN + bx * RPC + tid;

    // independent prologue: own row coords
    const float* xp = x1 + ((size_t)b * NN + r) * 3;
    float X0 = xp[0], X1 = xp[1], X2 = xp[2];

    pdl_wait();   // predecessor colsum wrote g_ss (earlier state transitively visible)

    for (int j = tid; j < MM; j += NT) {
        const float* yp = x2 + ((size_t)b * MM + j) * 3;
        float y0 = yp[0], y1 = yp[1], y2 = yp[2];
        float rr  = g_rR[cur][b * MM + j];
        float ssv = g_ss[b * MM + j];
        float ratio = fminf(__fdividef(rr, ssv + EPSF), 1.0f);
        tile[j] = make_float4(y0, y1, y2, lg2f(rr * ratio));
        float rrn = fmaxf(rr - ratio * ssv, 0.0f);
        tile2[j] = lg2f(rrn);
        if (bx == 0) g_rR[cur ^ 1][b * MM + j] = rrn;   // exact identity, no pair pass
    }
    __syncthreads();

    float rl = g_rL[cur][b * NN + r];
    float sv = g_s[b * NN + r];
    float F  = __fdividef(rl, sv + EPSF);   // hoisted per-row factor

    float rs0 = 0.f, rs1 = 0.f, c0 = 0.f, c1 = 0.f, sn0 = 0.f, sn1 = 0.f;
    const float4* __restrict__ t2v = (const float4*)tile2;
    for (int m = m0; m < m0 + SEGL; m += 4) {
        float4 P0 = tile[m + 0], P1 = tile[m + 1], P2 = tile[m + 2], P3 = tile[m + 3];
        float4 T  = t2v[m >> 2];
        float dx0 = X0 - P0.x, dy0 = X1 - P0.y, dz0 = X2 - P0.z;
        float dx1 = X0 - P1.x, dy1 = X1 - P1.y, dz1 = X2 - P1.z;
        float dx2 = X0 - P2.x, dy2 = X1 - P2.y, dz2 = X2 - P2.z;
        float dx3 = X0 - P3.x, dy3 = X1 - P3.y, dz3 = X2 - P3.z;
        float d20 = fmaf(dx0, dx0, fmaf(dy0, dy0, dz0 * dz0));
        float d21 = fmaf(dx1, dx1, fmaf(dy1, dy1, dz1 * dz1));
        float d22 = fmaf(dx2, dx2, fmaf(dy2, dy2, dz2 * dz2));
        float d23 = fmaf(dx3, dx3, fmaf(dy3, dy3, dz3 * dz3));
        float t0 = fmaf(d20, q, P0.w);
        float t1 = fmaf(d21, q, P1.w);
        float t2 = fmaf(d22, q, P2.w);
        float t3 = fmaf(d23, q, P3.w);
        float tm = fmaxf(fmaxf(t0, t1), fmaxf(t2, t3));
        if (__ballot_sync(0xffffffffu, tm > TMIN) != 0u) {
            float w0 = ex2f(t0), w1 = ex2f(t1), w2 = ex2f(t2), w3 = ex2f(t3);
            rs0 += w0 + w2; rs1 += w1 + w3;
            c0 = fmaf(w0, sqrt_apx(d20), c0);
            c1 = fmaf(w1, sqrt_apx(d21), c1);
            c0 = fmaf(w2, sqrt_apx(d22), c0);
            c1 = fmaf(w3, sqrt_apx(d23), c1);
        }
        float u0 = fmaf(d20, q2, T.x);
        float u1 = fmaf(d21, q2, T.y);
        float u2 = fmaf(d22, q2, T.z);
        float u3 = fmaf(d23, q2, T.w);
        float um = fmaxf(fmaxf(u0, u1), fmaxf(u2, u3));
        if (__ballot_sync(0xffffffffu, um > TMIN) != 0u) {
            sn0 += ex2f(u0) + ex2f(u2);
            sn1 += ex2f(u1) + ex2f(u3);
        }
    }

    // cost: scale by F per-thread, shuffle reduce
    float c = (c0 + c1) * F;
#pragma unroll
    for (int off = 16; off > 0; off >>= 1)
        c += __shfl_down_sync(0xffffffffu, c, off);
    if (lane == 0) cwarp[wid] = c;

    red[tid] = rs0 + rs1;
    __syncthreads();
    if (tid < RPC) {
        float v = 0.f;
#pragma unroll
        for (int k = 0; k < SEGS; k++) v += red[tid + (k << 7)];
        g_rL[cur ^ 1][rown] = fmaxf(rl - v * F, 0.0f);   // tid<RPC owns row r
    }
    __syncthreads();
    red[tid] = sn0 + sn1;
    __syncthreads();
    if (tid < RPC) {
        float v = 0.f;
#pragma unroll
        for (int k = 0; k < SEGS; k++) v += red[tid + (k << 7)];
        g_s[rown] = v;                                   // rowsum for level i+1
    }
    if (wid == 0) {
        float v = cwarp[lane];
#pragma unroll
        for (int off = 16; off > 0; off >>= 1)
            v += __shfl_down_sync(0xffffffffu, v, off);
        if (lane == 0) atomicAdd(&out[b], v);
    }
}

// ---------------- level 9 (L=0): analytic s/ss, single cost pass ----------------
__global__ void __launch_bounds__(NT, 1)
k_last(const float* __restrict__ x1, const float* __restrict__ x2,
       int cur, float* __restrict__ out) {
    __shared__ float4 tile[MM];
    __shared__ float  red[NT];
    __shared__ float  cwarp[NT / 32];
    __shared__ float  SLs;
    pdl_trigger();
    const int b = blockIdx.y, bx = blockIdx.x, tid = threadIdx.x;
    const int lane = tid & 31, wid = tid >> 5;
    const int r  = bx * RPC + (tid & (RPC - 1));
    const int m0 = (tid >> 7) * SEGL;

    const float* xp = x1 + ((size_t)b * NN + r) * 3;
    float X0 = xp[0], X1 = xp[1], X2 = xp[2];

    pdl_wait();

    const float* rR = g_rR[cur] + b * MM;
    const float* rL = g_rL[cur] + b * NN;
    const float* sp = g_s + b * NN;   // s[n] = sum rR (from fused(8), q2=0)

    float acc = 0.f;
    for (int j = tid; j < NN; j += NT)
        acc += __fdividef(rL[j], sp[j] + EPSF);
    red[tid] = acc;
    __syncthreads();
    if (tid < 32) {
        float v = 0.f;
#pragma unroll
        for (int k = 0; k < NT / 32; k++) v += red[tid + k * 32];
#pragma unroll
        for (int off = 16; off > 0; off >>= 1)
            v += __shfl_down_sync(0xffffffffu, v, off);
        if (tid == 0) SLs = v;
    }
    __syncthreads();
    const float SL = SLs;

    for (int j = tid; j < MM; j += NT) {
        const float* yp = x2 + ((size_t)b * MM + j) * 3;
        float rr = rR[j];
        float ratio = fminf(__fdividef(rr, fmaf(rr, SL, EPSF)), 1.0f);
        tile[j] = make_float4(yp[0], yp[1], yp[2], rr * ratio);
    }
    __syncthreads();

    float F = __fdividef(rL[r], sp[r] + EPSF);
    float c0 = 0.f, c1 = 0.f;
#pragma unroll 2
    for (int m = m0; m < m0 + SEGL; m += 2) {
        float4 P0 = tile[m + 0], P1 = tile[m + 1];
        float dx0 = X0 - P0.x, dy0 = X1 - P0.y, dz0 = X2 - P0.z;
        float dx1 = X0 - P1.x, dy1 = X1 - P1.y, dz1 = X2 - P1.z;
        float d20 = fmaf(dx0, dx0, fmaf(dy0, dy0, dz0 * dz0));
        float d21 = fmaf(dx1, dx1, fmaf(dy1, dy1, dz1 * dz1));
        c0 = fmaf(P0.w, sqrt_apx(d20), c0);
        c1 = fmaf(P1.w, sqrt_apx(d21), c1);
    }
    float c = (c0 + c1) * F;
#pragma unroll
    for (int off = 16; off > 0; off >>= 1)
        c += __shfl_down_sync(0xffffffffu, c, off);
    if (lane == 0) cwarp[wid] = c;
    __syncthreads();
    if (wid == 0) {
        float v = cwarp[lane];
#pragma unroll
        for (int off = 16; off > 0; off >>= 1)
            v += __shfl_down_sync(0xffffffffu, v, off);
        if (lane == 0) atomicAdd(&out[b], v);
    }
}

extern "C" void kernel_launch(void* const* d_in, const int* in_sizes, int n_in,
                              void* d_out, int out_size) {
    const float* x1 = (const float*)d_in[0];
    const float* x2 = (const float*)d_in[1];
    float* out = (float*)d_out;

    static const float levels[10] = {
        -16384.f, -4096.f, -1024.f, -256.f, -64.f, -16.f, -4.f, -1.f, -0.25f, 0.f
    };

    dim3 grid(NN / RPC, BB);   // (16, 8)

    cudaLaunchConfig_t cfg = {};
    cfg.gridDim = grid;
    cfg.blockDim = dim3(NT, 1, 1);
    cfg.dynamicSmemBytes = 0;
    cfg.stream = 0;
    cudaLaunchAttribute at;
    at.id = cudaLaunchAttributeProgrammaticStreamSerialization;
    at.val.programmaticStreamSerializationAllowed = 1;

    // first kernel: normal serialization (orders against prior graph replay)
    cfg.attrs = nullptr; cfg.numAttrs = 0;
    cudaLaunchKernelEx(&cfg, k_rowsum0, x1, x2, out, levels[0] * LOG2E);

    // rest: PDL-chained
    cfg.attrs = &at; cfg.numAttrs = 1;
    int cur = 0;
    for (int i = 0; i < 9; i++) {
        float q  = levels[i] * LOG2E;
        float q2 = levels[i + 1] * LOG2E;
        cudaLaunchKernelEx(&cfg, k_colsum, x1, x2, cur, q);
        cudaLaunchKernelEx(&cfg, k_fused, x1, x2, cur, q, q2, out);
        cur ^= 1;
    }
    cudaLaunchKernelEx(&cfg, k_last, x1, x2, cur, out);
}

// round 14
// speedup vs baseline: 1.0609x; 1.0032x over previous
#include <cuda_runtime.h>

// EMD approx-match (auction annealing), B=8, N=M=2048, 3-D points.
// R13: R12 (PDL multi-kernel) + Morton sort of both clouds (one extra kernel).
// Sorted order makes the existing 128-pair ballot groups spatially compact, so
// underflow skipping actually fires at levels -1024 .. -16. No box tests.
// Points stored as float4(x,y,z,|p|^2) in sorted order.

#define BB 8
#define NN 2048
#define MM 2048
#define EPSF 1e-9f
#define LOG2E 1.4426950408889634f
#define TMIN -126.0f

#define NT   1024
#define RPC  128
#define SEGS 8
#define SEGL (MM / SEGS)   // 256

__device__ float4 g_p1[BB * NN], g_p2[BB * MM];   // sorted points
__device__ float g_s [BB * NN];
__device__ float g_ss[BB * MM];
__device__ float g_rL[2][BB * NN];
__device__ float g_rR[2][BB * MM];

__device__ __forceinline__ float lg2f(float x) {
    float r; asm("lg2.approx.f32 %0, %1;" : "=f"(r) : "f"(x)); return r;
}
__device__ __forceinline__ float ex2f(float x) {
    float r; asm("ex2.approx.f32 %0, %1;" : "=f"(r) : "f"(x)); return r;
}
__device__ __forceinline__ float sqrt_apx(float x) {
    float r; asm("sqrt.approx.f32 %0, %1;" : "=f"(r) : "f"(x)); return r;
}
__device__ __forceinline__ void pdl_trigger() {
    asm volatile("griddepcontrol.launch_dependents;");
}
__device__ __forceinline__ void pdl_wait() {
    asm volatile("griddepcontrol.wait;" ::: "memory");
}
__device__ __forceinline__ unsigned expand10(unsigned v) {
    v &= 1023u;
    v = (v | (v << 16)) & 0x030000FFu;
    v = (v | (v << 8))  & 0x0300F00Fu;
    v = (v | (v << 4))  & 0x030C30C3u;
    v = (v | (v << 2))  & 0x09249249u;
    return v;
}

// ---------------- Morton sort (one CTA per cloud per batch) + init ----------------
__global__ void __launch_bounds__(NT, 1)
k_sort(const float* __restrict__ x1, const float* __restrict__ x2,
       float* __restrict__ out) {
    __shared__ unsigned long long keys[NN];   // 16 KB
    const int b = blockIdx.y, bx = blockIdx.x, tid = threadIdx.x;

    const float* src = (bx == 0) ? x1 + (size_t)b * NN * 3
                                 : x2 + (size_t)b * MM * 3;
    float4* dst = (bx == 0) ? g_p1 + b * NN : g_p2 + b * MM;

    for (int j = tid; j < NN; j += NT) {
        float x = src[j * 3], y = src[j * 3 + 1], z = src[j * 3 + 2];
        unsigned ux = (unsigned)(int)fminf(fmaxf((x + 5.f) * 102.4f, 0.f), 1023.f);
        unsigned uy = (unsigned)(int)fminf(fmaxf((y + 5.f) * 102.4f, 0.f), 1023.f);
        unsigned uz = (unsigned)(int)fminf(fmaxf((z + 5.f) * 102.4f, 0.f), 1023.f);
        unsigned code = (expand10(ux) << 2) | (expand10(uy) << 1) | expand10(uz);
        keys[j] = ((unsigned long long)code << 11) | (unsigned)j;
    }
    // init state while keys settle
    if (bx == 0) {
        for (int j = tid; j < NN; j += NT) g_rL[0][b * NN + j] = 1.0f;
    } else {
        for (int j = tid; j < MM; j += NT) g_rR[0][b * MM + j] = 1.0f;
        if (tid == 0) out[b] = 0.0f;
    }
    __syncthreads();

    for (int k = 2; k <= NN; k <<= 1) {
        for (int jj = k >> 1; jj > 0; jj >>= 1) {
#pragma unroll 2
            for (int i2 = tid; i2 < NN; i2 += NT) {
                int ixj = i2 ^ jj;
                if (ixj > i2) {
                    bool up = ((i2 & k) == 0);
                    unsigned long long a = keys[i2], c = keys[ixj];
                    if ((a > c) == up) { keys[i2] = c; keys[ixj] = a; }
                }
            }
            __syncthreads();
        }
    }
    for (int j = tid; j < NN; j += NT) {
        int idx = (int)(keys[j] & 2047ull);
        float x = src[idx * 3], y = src[idx * 3 + 1], z = src[idx * 3 + 2];
        dst[j] = make_float4(x, y, z, fmaf(x, x, fmaf(y, y, z * z)));
    }
}

// ---------------- rowsum(level 0): rR==1 -> lg2 term = 0 ----------------
__global__ void __launch_bounds__(NT, 1)
k_rowsum0(float q) {
    __shared__ float4 tile[MM];
    __shared__ float  red[NT];
    pdl_trigger();
    const int b = blockIdx.y, bx = blockIdx.x, tid = threadIdx.x;
    const int r  = bx * RPC + (tid & (RPC - 1));
    const int m0 = (tid >> 7) * SEGL;
    const float n2q = -2.0f * q;

    pdl_wait();   // k_sort wrote g_p1/g_p2

    for (int j = tid; j < MM; j += NT) {
        float4 p = g_p2[b * MM + j];
        tile[j] = make_float4(n2q * p.x, n2q * p.y, n2q * p.z, q * p.w);
    }
    __syncthreads();

    float4 X = g_p1[b * NN + r];
    float a  = q * X.w;

    float s0 = 0.f, s1 = 0.f, s2 = 0.f, s3 = 0.f;
#pragma unroll 4
    for (int m = m0; m < m0 + SEGL; m += 4) {
        float4 P0 = tile[m + 0], P1 = tile[m + 1], P2 = tile[m + 2], P3 = tile[m + 3];
        float t0 = fmaf(X.x, P0.x, fmaf(X.y, P0.y, fmaf(X.z, P0.z, a + P0.w)));
        float t1 = fmaf(X.x, P1.x, fmaf(X.y, P1.y, fmaf(X.z, P1.z, a + P1.w)));
        float t2 = fmaf(X.x, P2.x, fmaf(X.y, P2.y, fmaf(X.z, P2.z, a + P2.w)));
        float t3 = fmaf(X.x, P3.x, fmaf(X.y, P3.y, fmaf(X.z, P3.z, a + P3.w)));
        float tm = fmaxf(fmaxf(t0, t1), fmaxf(t2, t3));
        if (__ballot_sync(0xffffffffu, tm > TMIN) != 0u) {
            s0 += ex2f(t0); s1 += ex2f(t1); s2 += ex2f(t2); s3 += ex2f(t3);
        }
    }
    red[tid] = (s0 + s1) + (s2 + s3);
    __syncthreads();
    if (tid < RPC) {
        float v = 0.f;
#pragma unroll
        for (int k = 0; k < SEGS; k++) v += red[tid + (k << 7)];
        g_s[(size_t)b * NN + bx * RPC + tid] = v;
    }
}

// ---------------- colsum: ss[b][m] ----------------
__global__ void __launch_bounds__(NT, 1)
k_colsum(int cur, float q) {
    __shared__ float4 tile[NN];
    __shared__ float  red[NT];
    pdl_trigger();
    const int b = blockIdx.y, bx = blockIdx.x, tid = threadIdx.x;
    const int mcol = bx * RPC + (tid & (RPC - 1));
    const int n0 = (tid >> 7) * SEGL;
    const float n2q = -2.0f * q;

    pdl_wait();   // predecessor wrote g_rL, g_s, g_rR

    for (int j = tid; j < NN; j += NT) {
        float4 p = g_p1[b * NN + j];
        float rl = g_rL[cur][b * NN + j];
        float sv = g_s[b * NN + j];
        float f  = __fdividef(rl, sv + EPSF);
        tile[j] = make_float4(n2q * p.x, n2q * p.y, n2q * p.z,
                              fmaf(q, p.w, lg2f(f)));
    }
    __syncthreads();

    float4 Y = g_p2[b * MM + mcol];
    float c = fmaf(q, Y.w, lg2f(g_rR[cur][b * MM + mcol]));

    float s0 = 0.f, s1 = 0.f, s2 = 0.f, s3 = 0.f;
#pragma unroll 4
    for (int n = n0; n < n0 + SEGL; n += 4) {
        float4 P0 = tile[n + 0], P1 = tile[n + 1], P2 = tile[n + 2], P3 = tile[n + 3];
        float t0 = fmaf(Y.x, P0.x, fmaf(Y.y, P0.y, fmaf(Y.z, P0.z, c + P0.w)));
        float t1 = fmaf(Y.x, P1.x, fmaf(Y.y, P1.y, fmaf(Y.z, P1.z, c + P1.w)));
        float t2 = fmaf(Y.x, P2.x, fmaf(Y.y, P2.y, fmaf(Y.z, P2.z, c + P2.w)));
        float t3 = fmaf(Y.x, P3.x, fmaf(Y.y, P3.y, fmaf(Y.z, P3.z, c + P3.w)));
        float tm = fmaxf(fmaxf(t0, t1), fmaxf(t2, t3));
        if (__ballot_sync(0xffffffffu, tm > TMIN) != 0u) {
            s0 += ex2f(t0); s1 += ex2f(t1); s2 += ex2f(t2); s3 += ex2f(t3);
        }
    }
    red[tid] = (s0 + s1) + (s2 + s3);
    __syncthreads();
    if (tid < RPC) {
        float v = 0.f;
#pragma unroll
        for (int k = 0; k < SEGS; k++) v += red[tid + (k << 7)];
        g_ss[b * MM + bx * RPC + tid] = v;
    }
}

// ---------------- fused: pass3(level i) + rowsum(level i+1) ----------------
__global__ void __launch_bounds__(NT, 1)
k_fused(int cur, float q, float q2, float* __restrict__ out) {
    __shared__ float4 tile[MM];
    __shared__ __align__(16) float tile2[MM];
    __shared__ float  red[NT];
    __shared__ float  cwarp[NT / 32];
    pdl_trigger();
    const int b = blockIdx.y, bx = blockIdx.x, tid = threadIdx.x;
    const int lane = tid & 31, wid = tid >> 5;
    const int r  = bx * RPC + (tid & (RPC - 1));
    const int m0 = (tid >> 7) * SEGL;
    const int rown = b * NN + bx * RPC + tid;

    pdl_wait();   // predecessor colsum wrote g_ss

    for (int j = tid; j < MM; j += NT) {
        float4 p = g_p2[b * MM + j];
        float rr  = g_rR[cur][b * MM + j];
        float ssv = g_ss[b * MM + j];
        float ratio = fminf(__fdividef(rr, ssv + EPSF), 1.0f);
        tile[j] = make_float4(p.x, p.y, p.z, lg2f(rr * ratio));
        float rrn = fmaxf(rr - ratio * ssv, 0.0f);
        tile2[j] = lg2f(rrn);
        if (bx == 0) g_rR[cur ^ 1][b * MM + j] = rrn;   // exact identity, no pair pass
    }
    __syncthreads();

    float4 X = g_p1[b * NN + r];
    float rl = g_rL[cur][b * NN + r];
    float sv = g_s[b * NN + r];
    float F  = __fdividef(rl, sv + EPSF);   // hoisted per-row factor

    float rs0 = 0.f, rs1 = 0.f, c0 = 0.f, c1 = 0.f, sn0 = 0.f, sn1 = 0.f;
    const float4* __restrict__ t2v = (const float4*)tile2;
    for (int m = m0; m < m0 + SEGL; m += 4) {
        float4 P0 = tile[m + 0], P1 = tile[m + 1], P2 = tile[m + 2], P3 = tile[m + 3];
        float4 T  = t2v[m >> 2];
        float dx0 = X.x - P0.x, dy0 = X.y - P0.y, dz0 = X.z - P0.z;
        float dx1 = X.x - P1.x, dy1 = X.y - P1.y, dz1 = X.z - P1.z;
        float dx2 = X.x - P2.x, dy2 = X.y - P2.y, dz2 = X.z - P2.z;
        float dx3 = X.x - P3.x, dy3 = X.y - P3.y, dz3 = X.z - P3.z;
        float d20 = fmaf(dx0, dx0, fmaf(dy0, dy0, dz0 * dz0));
        float d21 = fmaf(dx1, dx1, fmaf(dy1, dy1, dz1 * dz1));
        float d22 = fmaf(dx2, dx2, fmaf(dy2, dy2, dz2 * dz2));
        float d23 = fmaf(dx3, dx3, fmaf(dy3, dy3, dz3 * dz3));
        float t0 = fmaf(d20, q, P0.w);
        float t1 = fmaf(d21, q, P1.w);
        float t2 = fmaf(d22, q, P2.w);
        float t3 = fmaf(d23, q, P3.w);
        float tm = fmaxf(fmaxf(t0, t1), fmaxf(t2, t3));
        if (__ballot_sync(0xffffffffu, tm > TMIN) != 0u) {
            float w0 = ex2f(t0), w1 = ex2f(t1), w2 = ex2f(t2), w3 = ex2f(t3);
            rs0 += w0 + w2; rs1 += w1 + w3;
            c0 = fmaf(w0, sqrt_apx(d20), c0);
            c1 = fmaf(w1, sqrt_apx(d21), c1);
            c0 = fmaf(w2, sqrt_apx(d22), c0);
            c1 = fmaf(w3, sqrt_apx(d23), c1);
        }
        float u0 = fmaf(d20, q2, T.x);
        float u1 = fmaf(d21, q2, T.y);
        float u2 = fmaf(d22, q2, T.z);
        float u3 = fmaf(d23, q2, T.w);
        float um = fmaxf(fmaxf(u0, u1), fmaxf(u2, u3));
        if (__ballot_sync(0xffffffffu, um > TMIN) != 0u) {
            sn0 += ex2f(u0) + ex2f(u2);
            sn1 += ex2f(u1) + ex2f(u3);
        }
    }

    float c = (c0 + c1) * F;
#pragma unroll
    for (int off = 16; off > 0; off >>= 1)
        c += __shfl_down_sync(0xffffffffu, c, off);
    if (lane == 0) cwarp[wid] = c;

    red[tid] = rs0 + rs1;
    __syncthreads();
    if (tid < RPC) {
        float v = 0.f;
#pragma unroll
        for (int k = 0; k < SEGS; k++) v += red[tid + (k << 7)];
        g_rL[cur ^ 1][rown] = fmaxf(rl - v * F, 0.0f);   // tid<RPC owns row r
    }
    __syncthreads();
    red[tid] = sn0 + sn1;
    __syncthreads();
    if (tid < RPC) {
        float v = 0.f;
#pragma unroll
        for (int k = 0; k < SEGS; k++) v += red[tid + (k << 7)];
        g_s[rown] = v;                                   // rowsum for level i+1
    }
    if (wid == 0) {
        float v = cwarp[lane];
#pragma unroll
        for (int off = 16; off > 0; off >>= 1)
            v += __shfl_down_sync(0xffffffffu, v, off);
        if (lane == 0) atomicAdd(&out[b], v);
    }
}

// ---------------- level 9 (L=0): analytic s/ss, single cost pass ----------------
__global__ void __launch_bounds__(NT, 1)
k_last(int cur, float* __restrict__ out) {
    __shared__ float4 tile[MM];
    __shared__ float  red[NT];
    __shared__ float  cwarp[NT / 32];
    __shared__ float  SLs;
    pdl_trigger();
    const int b = blockIdx.y, bx = blockIdx.x, tid = threadIdx.x;
    const int lane = tid & 31, wid = tid >> 5;
    const int r  = bx * RPC + (tid & (RPC - 1));
    const int m0 = (tid >> 7) * SEGL;

    pdl_wait();

    const float* rR = g_rR[cur] + b * MM;
    const float* rL = g_rL[cur] + b * NN;
    const float* sp = g_s + b * NN;   // s[n] = sum rR (from fused(8), q2=0)

    float acc = 0.f;
    for (int j = tid; j < NN; j += NT)
        acc += __fdividef(rL[j], sp[j] + EPSF);
    red[tid] = acc;
    __syncthreads();
    if (tid < 32) {
        float v = 0.f;
#pragma unroll
        for (int k = 0; k < NT / 32; k++) v += red[tid + k * 32];
#pragma unroll
        for (int off = 16; off > 0; off >>= 1)
            v += __shfl_down_sync(0xffffffffu, v, off);
        if (tid == 0) SLs = v;
    }
    __syncthreads();
    const float SL = SLs;

    for (int j = tid; j < MM; j += NT) {
        float4 p = g_p2[b * MM + j];
        float rr = rR[j];
        float ratio = fminf(__fdividef(rr, fmaf(rr, SL, EPSF)), 1.0f);
        tile[j] = make_float4(p.x, p.y, p.z, rr * ratio);
    }
    __syncthreads();

    float4 X = g_p1[b * NN + r];
    float F = __fdividef(rL[r], sp[r] + EPSF);
    float c0 = 0.f, c1 = 0.f;
#pragma unroll 2
    for (int m = m0; m < m0 + SEGL; m += 2) {
        float4 P0 = tile[m + 0], P1 = tile[m + 1];
        float dx0 = X.x - P0.x, dy0 = X.y - P0.y, dz0 = X.z - P0.z;
        float dx1 = X.x - P1.x, dy1 = X.y - P1.y, dz1 = X.z - P1.z;
        float d20 = fmaf(dx0, dx0, fmaf(dy0, dy0, dz0 * dz0));
        float d21 = fmaf(dx1, dx1, fmaf(dy1, dy1, dz1 * dz1));
        c0 = fmaf(P0.w, sqrt_apx(d20), c0);
        c1 = fmaf(P1.w, sqrt_apx(d21), c1);
    }
    float c = (c0 + c1) * F;
#pragma unroll
    for (int off = 16; off > 0; off >>= 1)
        c += __shfl_down_sync(0xffffffffu, c, off);
    if (lane == 0) cwarp[wid] = c;
    __syncthreads();
    if (wid == 0) {
        float v = cwarp[lane];
#pragma unroll
        for (int off = 16; off > 0; off >>= 1)
            v += __shfl_down_sync(0xffffffffu, v, off);
        if (lane == 0) atomicAdd(&out[b], v);
    }
}

extern "C" void kernel_launch(void* const* d_in, const int* in_sizes, int n_in,
                              void* d_out, int out_size) {
    const float* x1 = (const float*)d_in[0];
    const float* x2 = (const float*)d_in[1];
    float* out = (float*)d_out;

    static const float levels[10] = {
        -16384.f, -4096.f, -1024.f, -256.f, -64.f, -16.f, -4.f, -1.f, -0.25f, 0.f
    };

    cudaLaunchConfig_t cfg = {};
    cfg.blockDim = dim3(NT, 1, 1);
    cfg.dynamicSmemBytes = 0;
    cfg.stream = 0;
    cudaLaunchAttribute at;
    at.id = cudaLaunchAttributeProgrammaticStreamSerialization;
    at.val.programmaticStreamSerializationAllowed = 1;

    // sort+init: normal serialization (orders against prior graph replay)
    cfg.gridDim = dim3(2, BB);
    cfg.attrs = nullptr; cfg.numAttrs = 0;
    cudaLaunchKernelEx(&cfg, k_sort, x1, x2, out);

    // rest: PDL-chained
    cfg.gridDim = dim3(NN / RPC, BB);   // (16, 8)
    cfg.attrs = &at; cfg.numAttrs = 1;
    cudaLaunchKernelEx(&cfg, k_rowsum0, levels[0] * LOG2E);

    int cur = 0;
    for (int i = 0; i < 9; i++) {
        float q  = levels[i] * LOG2E;
        float q2 = levels[i + 1] * LOG2E;
        cudaLaunchKernelEx(&cfg, k_colsum, cur, q);
        cudaLaunchKernelEx(&cfg, k_fused, cur, q, q2, out);
        cur ^= 1;
    }
    cudaLaunchKernelEx(&cfg, k_last, cur, out);
}

// round 15
// speedup vs baseline: 1.1978x; 1.1290x over previous
#include <cuda_runtime.h>

// EMD approx-match (auction annealing), B=8, N=M=2048, 3-D points.
// R14 = R13 (PDL multi-kernel + Morton sort) +
//  (1) packed f32x2 math (sm_103a) in all pair loops: column-pair tiles
//      (x0,x1,y0,y1)/(z0,z1,w0,w1), one LDS.128 = two packed operands.
//  (2) LAST specialization of fused(i=8): q2==0 -> u-stream deleted;
//      k_last uses exact scalars S2 = sum(rrn), SL = sum(rL)/(S2+eps).

#define BB 8
#define NN 2048
#define MM 2048
#define EPSF 1e-9f
#define LOG2E 1.4426950408889634f
#define TMIN -126.0f

#define NT   1024
#define RPC  128
#define SEGS 8
#define SEGL (MM / SEGS)   // 256 cols = 128 pairs per thread

typedef unsigned long long u64;

__device__ float4 g_p1[BB * NN], g_p2[BB * MM];   // sorted (x,y,z,|p|^2)
__device__ float g_s [BB * NN];
__device__ float g_ss[BB * MM];
__device__ float g_rL[2][BB * NN];
__device__ float g_rR[2][BB * MM];

__device__ __forceinline__ float lg2f(float x) {
    float r; asm("lg2.approx.f32 %0, %1;" : "=f"(r) : "f"(x)); return r;
}
__device__ __forceinline__ float ex2f(float x) {
    float r; asm("ex2.approx.f32 %0, %1;" : "=f"(r) : "f"(x)); return r;
}
__device__ __forceinline__ float sqrt_apx(float x) {
    float r; asm("sqrt.approx.f32 %0, %1;" : "=f"(r) : "f"(x)); return r;
}
__device__ __forceinline__ void pdl_trigger() {
    asm volatile("griddepcontrol.launch_dependents;");
}
__device__ __forceinline__ void pdl_wait() {
    asm volatile("griddepcontrol.wait;" ::: "memory");
}
// ---- packed f32x2 helpers (sm_100+) ----
__device__ __forceinline__ u64 pk2(float a, float b) {
    u64 r; asm("mov.b64 %0, {%1, %2};" : "=l"(r) : "f"(a), "f"(b)); return r;
}
__device__ __forceinline__ void upk2(u64 p, float& a, float& b) {
    asm("mov.b64 {%0, %1}, %2;" : "=f"(a), "=f"(b) : "l"(p));
}
__device__ __forceinline__ u64 addx2(u64 a, u64 b) {
    u64 r; asm("add.rn.f32x2 %0, %1, %2;" : "=l"(r) : "l"(a), "l"(b)); return r;
}
__device__ __forceinline__ u64 mulx2(u64 a, u64 b) {
    u64 r; asm("mul.rn.f32x2 %0, %1, %2;" : "=l"(r) : "l"(a), "l"(b)); return r;
}
__device__ __forceinline__ u64 fmx2(u64 a, u64 b, u64 c) {
    u64 r; asm("fma.rn.f32x2 %0, %1, %2, %3;" : "=l"(r) : "l"(a), "l"(b), "l"(c)); return r;
}
__device__ __forceinline__ unsigned expand10(unsigned v) {
    v &= 1023u;
    v = (v | (v << 16)) & 0x030000FFu;
    v = (v | (v << 8))  & 0x0300F00Fu;
    v = (v | (v << 4))  & 0x030C30C3u;
    v = (v | (v << 2))  & 0x09249249u;
    return v;
}

// ---------------- Morton sort (one CTA per cloud per batch) + init ----------------
__global__ void __launch_bounds__(NT, 1)
k_sort(const float* __restrict__ x1, const float* __restrict__ x2,
       float* __restrict__ out) {
    __shared__ unsigned long long keys[NN];
    const int b = blockIdx.y, bx = blockIdx.x, tid = threadIdx.x;

    const float* src = (bx == 0) ? x1 + (size_t)b * NN * 3
                                 : x2 + (size_t)b * MM * 3;
    float4* dst = (bx == 0) ? g_p1 + b * NN : g_p2 + b * MM;

    for (int j = tid; j < NN; j += NT) {
        float x = src[j * 3], y = src[j * 3 + 1], z = src[j * 3 + 2];
        unsigned ux = (unsigned)(int)fminf(fmaxf((x + 5.f) * 102.4f, 0.f), 1023.f);
        unsigned uy = (unsigned)(int)fminf(fmaxf((y + 5.f) * 102.4f, 0.f), 1023.f);
        unsigned uz = (unsigned)(int)fminf(fmaxf((z + 5.f) * 102.4f, 0.f), 1023.f);
        unsigned code = (expand10(ux) << 2) | (expand10(uy) << 1) | expand10(uz);
        keys[j] = ((unsigned long long)code << 11) | (unsigned)j;
    }
    if (bx == 0) {
        for (int j = tid; j < NN; j += NT) g_rL[0][b * NN + j] = 1.0f;
    } else {
        for (int j = tid; j < MM; j += NT) g_rR[0][b * MM + j] = 1.0f;
        if (tid == 0) out[b] = 0.0f;
    }
    __syncthreads();

    for (int k = 2; k <= NN; k <<= 1) {
        for (int jj = k >> 1; jj > 0; jj >>= 1) {
#pragma unroll 2
            for (int i2 = tid; i2 < NN; i2 += NT) {
                int ixj = i2 ^ jj;
                if (ixj > i2) {
                    bool up = ((i2 & k) == 0);
                    unsigned long long a = keys[i2], c = keys[ixj];
                    if ((a > c) == up) { keys[i2] = c; keys[ixj] = a; }
                }
            }
            __syncthreads();
        }
    }
    for (int j = tid; j < NN; j += NT) {
        int idx = (int)(keys[j] & 2047ull);
        float x = src[idx * 3], y = src[idx * 3 + 1], z = src[idx * 3 + 2];
        dst[j] = make_float4(x, y, z, fmaf(x, x, fmaf(y, y, z * z)));
    }
}

// ---------------- rowsum(level 0): rR==1 -> lg2 term = 0 ----------------
__global__ void __launch_bounds__(NT, 1)
k_rowsum0(float q) {
    __shared__ float4 tileA[MM / 2];   // (n2q*x0, n2q*x1, n2q*y0, n2q*y1)
    __shared__ float4 tileB[MM / 2];   // (n2q*z0, n2q*z1, w0, w1)
    __shared__ float  red[NT];
    pdl_trigger();
    const int b = blockIdx.y, bx = blockIdx.x, tid = threadIdx.x;
    const int r  = bx * RPC + (tid & (RPC - 1));
    const int p0 = ((tid >> 7) * SEGL) >> 1;
    const float n2q = -2.0f * q;

    pdl_wait();   // k_sort wrote g_p1/g_p2

    {
        float4 pa = g_p2[b * MM + 2 * tid];
        float4 pb = g_p2[b * MM + 2 * tid + 1];
        tileA[tid] = make_float4(n2q * pa.x, n2q * pb.x, n2q * pa.y, n2q * pb.y);
        tileB[tid] = make_float4(n2q * pa.z, n2q * pb.z, q * pa.w, q * pb.w);
    }
    __syncthreads();

    float4 X = g_p1[b * NN + r];
    u64 Xx = pk2(X.x, X.x), Xy = pk2(X.y, X.y), Xz = pk2(X.z, X.z);
    u64 ap = pk2(q * X.w, q * X.w);

    float s0 = 0.f, s1 = 0.f;
    for (int p = p0; p < p0 + SEGL / 2; p += 2) {
        float4 A0 = tileA[p], B0 = tileB[p];
        float4 A1 = tileA[p + 1], B1 = tileB[p + 1];
        u64 ta = fmx2(Xx, pk2(A0.x, A0.y),
                 fmx2(Xy, pk2(A0.z, A0.w),
                 fmx2(Xz, pk2(B0.x, B0.y), addx2(ap, pk2(B0.z, B0.w)))));
        u64 tb = fmx2(Xx, pk2(A1.x, A1.y),
                 fmx2(Xy, pk2(A1.z, A1.w),
                 fmx2(Xz, pk2(B1.x, B1.y), addx2(ap, pk2(B1.z, B1.w)))));
        float t0, t1, t2, t3; upk2(ta, t0, t1); upk2(tb, t2, t3);
        float tm = fmaxf(fmaxf(t0, t1), fmaxf(t2, t3));
        if (__ballot_sync(0xffffffffu, tm > TMIN) != 0u) {
            s0 += ex2f(t0) + ex2f(t2);
            s1 += ex2f(t1) + ex2f(t3);
        }
    }
    red[tid] = s0 + s1;
    __syncthreads();
    if (tid < RPC) {
        float v = 0.f;
#pragma unroll
        for (int k = 0; k < SEGS; k++) v += red[tid + (k << 7)];
        g_s[(size_t)b * NN + bx * RPC + tid] = v;
    }
}

// ---------------- colsum: ss[b][m] ----------------
__global__ void __launch_bounds__(NT, 1)
k_colsum(int cur, float q) {
    __shared__ float4 tileA[NN / 2];
    __shared__ float4 tileB[NN / 2];
    __shared__ float  red[NT];
    pdl_trigger();
    const int b = blockIdx.y, bx = blockIdx.x, tid = threadIdx.x;
    const int mcol = bx * RPC + (tid & (RPC - 1));
    const int p0 = ((tid >> 7) * SEGL) >> 1;
    const float n2q = -2.0f * q;

    pdl_wait();   // predecessor wrote g_rL, g_s, g_rR

    {
        float4 pa = g_p1[b * NN + 2 * tid];
        float4 pb = g_p1[b * NN + 2 * tid + 1];
        float rla = g_rL[cur][b * NN + 2 * tid];
        float rlb = g_rL[cur][b * NN + 2 * tid + 1];
        float sva = g_s[b * NN + 2 * tid];
        float svb = g_s[b * NN + 2 * tid + 1];
        float wa = fmaf(q, pa.w, lg2f(__fdividef(rla, sva + EPSF)));
        float wb = fmaf(q, pb.w, lg2f(__fdividef(rlb, svb + EPSF)));
        tileA[tid] = make_float4(n2q * pa.x, n2q * pb.x, n2q * pa.y, n2q * pb.y);
        tileB[tid] = make_float4(n2q * pa.z, n2q * pb.z, wa, wb);
    }
    __syncthreads();

    float4 Y = g_p2[b * MM + mcol];
    float c = fmaf(q, Y.w, lg2f(g_rR[cur][b * MM + mcol]));
    u64 Yx = pk2(Y.x, Y.x), Yy = pk2(Y.y, Y.y), Yz = pk2(Y.z, Y.z);
    u64 cp = pk2(c, c);

    float s0 = 0.f, s1 = 0.f;
    for (int p = p0; p < p0 + SEGL / 2; p += 2) {
        float4 A0 = tileA[p], B0 = tileB[p];
        float4 A1 = tileA[p + 1], B1 = tileB[p + 1];
        u64 ta = fmx2(Yx, pk2(A0.x, A0.y),
                 fmx2(Yy, pk2(A0.z, A0.w),
                 fmx2(Yz, pk2(B0.x, B0.y), addx2(cp, pk2(B0.z, B0.w)))));
        u64 tb = fmx2(Yx, pk2(A1.x, A1.y),
                 fmx2(Yy, pk2(A1.z, A1.w),
                 fmx2(Yz, pk2(B1.x, B1.y), addx2(cp, pk2(B1.z, B1.w)))));
        float t0, t1, t2, t3; upk2(ta, t0, t1); upk2(tb, t2, t3);
        float tm = fmaxf(fmaxf(t0, t1), fmaxf(t2, t3));
        if (__ballot_sync(0xffffffffu, tm > TMIN) != 0u) {
            s0 += ex2f(t0) + ex2f(t2);
            s1 += ex2f(t1) + ex2f(t3);
        }
    }
    red[tid] = s0 + s1;
    __syncthreads();
    if (tid < RPC) {
        float v = 0.f;
#pragma unroll
        for (int k = 0; k < SEGS; k++) v += red[tid + (k << 7)];
        g_ss[b * MM + bx * RPC + tid] = v;
    }
}

// ---------------- fused: pass3(level i) + rowsum(level i+1) ----------------
// LAST (q2==0): u-stream is exp2(lg2(rrn)) == rrn, row-independent -> deleted;
// k_last recovers S2 = sum(rrn) itself.
template <bool LAST>
__global__ void __launch_bounds__(NT, 1)
k_fused(int cur, float q, float q2, float* __restrict__ out) {
    __shared__ float4 tileA[MM / 2];   // (-x0,-x1,-y0,-y1)
    __shared__ float4 tileB[MM / 2];   // (-z0,-z1, lg2(rr*ratio)0, ..1)
    __shared__ __align__(16) float tile2[MM];   // lg2(rrn) per col (unused if LAST)
    __shared__ float  red[NT];
    __shared__ float  cwarp[NT / 32];
    pdl_trigger();
    const int b = blockIdx.y, bx = blockIdx.x, tid = threadIdx.x;
    const int lane = tid & 31, wid = tid >> 5;
    const int r  = bx * RPC + (tid & (RPC - 1));
    const int p0 = ((tid >> 7) * SEGL) >> 1;
    const int rown = b * NN + bx * RPC + tid;

    pdl_wait();   // predecessor colsum wrote g_ss

    {
        float4 pa = g_p2[b * MM + 2 * tid];
        float4 pb = g_p2[b * MM + 2 * tid + 1];
        float rra = g_rR[cur][b * MM + 2 * tid];
        float rrb = g_rR[cur][b * MM + 2 * tid + 1];
        float ssa = g_ss[b * MM + 2 * tid];
        float ssb = g_ss[b * MM + 2 * tid + 1];
        float raa = fminf(__fdividef(rra, ssa + EPSF), 1.0f);
        float rab = fminf(__fdividef(rrb, ssb + EPSF), 1.0f);
        tileA[tid] = make_float4(-pa.x, -pb.x, -pa.y, -pb.y);
        tileB[tid] = make_float4(-pa.z, -pb.z, lg2f(rra * raa), lg2f(rrb * rab));
        float rrna = fmaxf(rra - raa * ssa, 0.0f);
        float rrnb = fmaxf(rrb - rab * ssb, 0.0f);
        if (!LAST) {
            tile2[2 * tid]     = lg2f(rrna);
            tile2[2 * tid + 1] = lg2f(rrnb);
        }
        if (bx == 0) {
            g_rR[cur ^ 1][b * MM + 2 * tid]     = rrna;   // exact identity
            g_rR[cur ^ 1][b * MM + 2 * tid + 1] = rrnb;
        }
    }
    __syncthreads();

    float4 X = g_p1[b * NN + r];
    float rl = g_rL[cur][b * NN + r];
    float sv = g_s[b * NN + r];
    float F  = __fdividef(rl, sv + EPSF);   // hoisted per-row factor
    u64 Xx = pk2(X.x, X.x), Xy = pk2(X.y, X.y), Xz = pk2(X.z, X.z);
    u64 qp = pk2(q, q), q2p = pk2(q2, q2);

    float rs0 = 0.f, rs1 = 0.f, c0 = 0.f, c1 = 0.f, sn0 = 0.f, sn1 = 0.f;
    const float4* __restrict__ t2v = (const float4*)tile2;
    for (int p = p0; p < p0 + SEGL / 2; p += 2) {
        float4 A0 = tileA[p], B0 = tileB[p];
        float4 A1 = tileA[p + 1], B1 = tileB[p + 1];
        u64 dxa = addx2(Xx, pk2(A0.x, A0.y));
        u64 dya = addx2(Xy, pk2(A0.z, A0.w));
        u64 dza = addx2(Xz, pk2(B0.x, B0.y));
        u64 d2a = fmx2(dxa, dxa, fmx2(dya, dya, mulx2(dza, dza)));
        u64 dxb = addx2(Xx, pk2(A1.x, A1.y));
        u64 dyb = addx2(Xy, pk2(A1.z, A1.w));
        u64 dzb = addx2(Xz, pk2(B1.x, B1.y));
        u64 d2b = fmx2(dxb, dxb, fmx2(dyb, dyb, mulx2(dzb, dzb)));
        u64 ta = fmx2(d2a, qp, pk2(B0.z, B0.w));
        u64 tb = fmx2(d2b, qp, pk2(B1.z, B1.w));
        float t0, t1, t2, t3; upk2(ta, t0, t1); upk2(tb, t2, t3);
        float d20, d21, d22, d23; upk2(d2a, d20, d21); upk2(d2b, d22, d23);
        float tm = fmaxf(fmaxf(t0, t1), fmaxf(t2, t3));
        if (__ballot_sync(0xffffffffu, tm > TMIN) != 0u) {
            float w0 = ex2f(t0), w1 = ex2f(t1), w2 = ex2f(t2), w3 = ex2f(t3);
            rs0 += w0 + w2; rs1 += w1 + w3;
            c0 = fmaf(w0, sqrt_apx(d20), c0);
            c1 = fmaf(w1, sqrt_apx(d21), c1);
            c0 = fmaf(w2, sqrt_apx(d22), c0);
            c1 = fmaf(w3, sqrt_apx(d23), c1);
        }
        if (!LAST) {
            float4 T4 = t2v[p >> 1];
            u64 ua = fmx2(d2a, q2p, pk2(T4.x, T4.y));
            u64 ub = fmx2(d2b, q2p, pk2(T4.z, T4.w));
            float u0, u1, u2, u3; upk2(ua, u0, u1); upk2(ub, u2, u3);
            float um = fmaxf(fmaxf(u0, u1), fmaxf(u2, u3));
            if (__ballot_sync(0xffffffffu, um > TMIN) != 0u) {
                sn0 += ex2f(u0) + ex2f(u2);
                sn1 += ex2f(u1) + ex2f(u3);
            }
        }
    }

    float c = (c0 + c1) * F;
#pragma unroll
    for (int off = 16; off > 0; off >>= 1)
        c += __shfl_down_sync(0xffffffffu, c, off);
    if (lane == 0) cwarp[wid] = c;

    red[tid] = rs0 + rs1;
    __syncthreads();
    if (tid < RPC) {
        float v = 0.f;
#pragma unroll
        for (int k = 0; k < SEGS; k++) v += red[tid + (k << 7)];
        g_rL[cur ^ 1][rown] = fmaxf(rl - v * F, 0.0f);   // tid<RPC owns row r
    }
    if (!LAST) {
        __syncthreads();
        red[tid] = sn0 + sn1;
        __syncthreads();
        if (tid < RPC) {
            float v = 0.f;
#pragma unroll
            for (int k = 0; k < SEGS; k++) v += red[tid + (k << 7)];
            g_s[rown] = v;                               // rowsum for level i+1
        }
    }
    if (wid == 0) {
        float v = cwarp[lane];
#pragma unroll
        for (int off = 16; off > 0; off >>= 1)
            v += __shfl_down_sync(0xffffffffu, v, off);
        if (lane == 0) atomicAdd(&out[b], v);
    }
}

// ---------------- level 9 (L=0): analytic, single cost pass ----------------
// s[n] = S2 = sum_m rR (scalar), SL = sum_n rL / (S2+eps) (scalar).
__global__ void __launch_bounds__(NT, 1)
k_last(int cur, float* __restrict__ out) {
    __shared__ float4 tile[MM];
    __shared__ float  red[NT];
    __shared__ float  cwarp[NT / 32];
    __shared__ float  sh2[2];
    pdl_trigger();
    const int b = blockIdx.y, bx = blockIdx.x, tid = threadIdx.x;
    const int lane = tid & 31, wid = tid >> 5;
    const int r  = bx * RPC + (tid & (RPC - 1));
    const int m0 = (tid >> 7) * SEGL;

    pdl_wait();

    const float* rR = g_rR[cur] + b * MM;
    const float* rL = g_rL[cur] + b * NN;

    float aL = 0.f, aR = 0.f;
    for (int j = tid; j < NN; j += NT) { aL += rL[j]; aR += rR[j]; }
    red[tid] = aL;
    __syncthreads();
    if (tid < 32) {
        float v = 0.f;
#pragma unroll
        for (int k = 0; k < NT / 32; k++) v += red[tid + k * 32];
#pragma unroll
        for (int off = 16; off > 0; off >>= 1)
            v += __shfl_down_sync(0xffffffffu, v, off);
        if (tid == 0) sh2[0] = v;
    }
    __syncthreads();
    red[tid] = aR;
    __syncthreads();
    if (tid < 32) {
        float v = 0.f;
#pragma unroll
        for (int k = 0; k < NT / 32; k++) v += red[tid + k * 32];
#pragma unroll
        for (int off = 16; off > 0; off >>= 1)
            v += __shfl_down_sync(0xffffffffu, v, off);
        if (tid == 0) sh2[1] = v;
    }
    __syncthreads();
    const float S2 = sh2[1];
    const float SL = __fdividef(sh2[0], S2 + EPSF);

    for (int j = tid; j < MM; j += NT) {
        float4 p = g_p2[b * MM + j];
        float rr = rR[j];
        float ratio = fminf(__fdividef(rr, fmaf(rr, SL, EPSF)), 1.0f);
        tile[j] = make_float4(p.x, p.y, p.z, rr * ratio);
    }
    __syncthreads();

    float4 X = g_p1[b * NN + r];
    float F = __fdividef(rL[r], S2 + EPSF);
    float c0 = 0.f, c1 = 0.f;
#pragma unroll 2
    for (int m = m0; m < m0 + SEGL; m += 2) {
        float4 P0 = tile[m + 0], P1 = tile[m + 1];
        float dx0 = X.x - P0.x, dy0 = X.y - P0.y, dz0 = X.z - P0.z;
        float dx1 = X.x - P1.x, dy1 = X.y - P1.y, dz1 = X.z - P1.z;
        float d20 = fmaf(dx0, dx0, fmaf(dy0, dy0, dz0 * dz0));
        float d21 = fmaf(dx1, dx1, fmaf(dy1, dy1, dz1 * dz1));
        c0 = fmaf(P0.w, sqrt_apx(d20), c0);
        c1 = fmaf(P1.w, sqrt_apx(d21), c1);
    }
    float c = (c0 + c1) * F;
#pragma unroll
    for (int off = 16; off > 0; off >>= 1)
        c += __shfl_down_sync(0xffffffffu, c, off);
    if (lane == 0) cwarp[wid] = c;
    __syncthreads();
    if (wid == 0) {
        float v = cwarp[lane];
#pragma unroll
        for (int off = 16; off > 0; off >>= 1)
            v += __shfl_down_sync(0xffffffffu, v, off);
        if (lane == 0) atomicAdd(&out[b], v);
    }
}

extern "C" void kernel_launch(void* const* d_in, const int* in_sizes, int n_in,
                              void* d_out, int out_size) {
    const float* x1 = (const float*)d_in[0];
    const float* x2 = (const float*)d_in[1];
    float* out = (float*)d_out;

    static const float levels[10] = {
        -16384.f, -4096.f, -1024.f, -256.f, -64.f, -16.f, -4.f, -1.f, -0.25f, 0.f
    };

    cudaLaunchConfig_t cfg = {};
    cfg.blockDim = dim3(NT, 1, 1);
    cfg.dynamicSmemBytes = 0;
    cfg.stream = 0;
    cudaLaunchAttribute at;
    at.id = cudaLaunchAttributeProgrammaticStreamSerialization;
    at.val.programmaticStreamSerializationAllowed = 1;

    // sort+init: normal serialization (orders against prior graph replay)
    cfg.gridDim = dim3(2, BB);
    cfg.attrs = nullptr; cfg.numAttrs = 0;
    cudaLaunchKernelEx(&cfg, k_sort, x1, x2, out);

    // rest: PDL-chained
    cfg.gridDim = dim3(NN / RPC, BB);   // (16, 8)
    cfg.attrs = &at; cfg.numAttrs = 1;
    cudaLaunchKernelEx(&cfg, k_rowsum0, levels[0] * LOG2E);

    int cur = 0;
    for (int i = 0; i < 9; i++) {
        float q  = levels[i] * LOG2E;
        float q2 = levels[i + 1] * LOG2E;
        cudaLaunchKernelEx(&cfg, k_colsum, cur, q);
        if (i < 8) cudaLaunchKernelEx(&cfg, k_fused<false>, cur, q, q2, out);
        else       cudaLaunchKernelEx(&cfg, k_fused<true >, cur, q, q2, out);
        cur ^= 1;
    }
    cudaLaunchKernelEx(&cfg, k_last, cur, out);
}

// round 16
// speedup vs baseline: 1.2098x; 1.0100x over previous
#include <cuda_runtime.h>

// EMD approx-match (auction annealing), B=8, N=M=2048, 3-D points.
// R15 = R14 + tiles stored as ulonglong2 whose halves ARE the packed f32x2
// operands (zero repack movs in the pair loops; cuts the ALU pipe load),
// and packed-f32x2 k_last cost loop.

#define BB 8
#define NN 2048
#define MM 2048
#define EPSF 1e-9f
#define LOG2E 1.4426950408889634f
#define TMIN -126.0f

#define NT   1024
#define RPC  128
#define SEGS 8
#define SEGL (MM / SEGS)   // 256 cols = 128 pairs per thread

typedef unsigned long long u64;

__device__ float4 g_p1[BB * NN], g_p2[BB * MM];   // sorted (x,y,z,|p|^2)
__device__ float g_s [BB * NN];
__device__ float g_ss[BB * MM];
__device__ float g_rL[2][BB * NN];
__device__ float g_rR[2][BB * MM];

__device__ __forceinline__ float lg2f(float x) {
    float r; asm("lg2.approx.f32 %0, %1;" : "=f"(r) : "f"(x)); return r;
}
__device__ __forceinline__ float ex2f(float x) {
    float r; asm("ex2.approx.f32 %0, %1;" : "=f"(r) : "f"(x)); return r;
}
__device__ __forceinline__ float sqrt_apx(float x) {
    float r; asm("sqrt.approx.f32 %0, %1;" : "=f"(r) : "f"(x)); return r;
}
__device__ __forceinline__ void pdl_trigger() {
    asm volatile("griddepcontrol.launch_dependents;");
}
__device__ __forceinline__ void pdl_wait() {
    asm volatile("griddepcontrol.wait;" ::: "memory");
}
// ---- packed f32x2 helpers (sm_100+) ----
__device__ __forceinline__ u64 pk2(float a, float b) {
    u64 r; asm("mov.b64 %0, {%1, %2};" : "=l"(r) : "f"(a), "f"(b)); return r;
}
__device__ __forceinline__ void upk2(u64 p, float& a, float& b) {
    asm("mov.b64 {%0, %1}, %2;" : "=f"(a), "=f"(b) : "l"(p));
}
__device__ __forceinline__ u64 addx2(u64 a, u64 b) {
    u64 r; asm("add.rn.f32x2 %0, %1, %2;" : "=l"(r) : "l"(a), "l"(b)); return r;
}
__device__ __forceinline__ u64 mulx2(u64 a, u64 b) {
    u64 r; asm("mul.rn.f32x2 %0, %1, %2;" : "=l"(r) : "l"(a), "l"(b)); return r;
}
__device__ __forceinline__ u64 fmx2(u64 a, u64 b, u64 c) {
    u64 r; asm("fma.rn.f32x2 %0, %1, %2, %3;" : "=l"(r) : "l"(a), "l"(b), "l"(c)); return r;
}
__device__ __forceinline__ unsigned expand10(unsigned v) {
    v &= 1023u;
    v = (v | (v << 16)) & 0x030000FFu;
    v = (v | (v << 8))  & 0x0300F00Fu;
    v = (v | (v << 4))  & 0x030C30C3u;
    v = (v | (v << 2))  & 0x09249249u;
    return v;
}

// ---------------- Morton sort (one CTA per cloud per batch) + init ----------------
__global__ void __launch_bounds__(NT, 1)
k_sort(const float* __restrict__ x1, const float* __restrict__ x2,
       float* __restrict__ out) {
    __shared__ unsigned long long keys[NN];
    const int b = blockIdx.y, bx = blockIdx.x, tid = threadIdx.x;

    const float* src = (bx == 0) ? x1 + (size_t)b * NN * 3
                                 : x2 + (size_t)b * MM * 3;
    float4* dst = (bx == 0) ? g_p1 + b * NN : g_p2 + b * MM;

    for (int j = tid; j < NN; j += NT) {
        float x = src[j * 3], y = src[j * 3 + 1], z = src[j * 3 + 2];
        unsigned ux = (unsigned)(int)fminf(fmaxf((x + 5.f) * 102.4f, 0.f), 1023.f);
        unsigned uy = (unsigned)(int)fminf(fmaxf((y + 5.f) * 102.4f, 0.f), 1023.f);
        unsigned uz = (unsigned)(int)fminf(fmaxf((z + 5.f) * 102.4f, 0.f), 1023.f);
        unsigned code = (expand10(ux) << 2) | (expand10(uy) << 1) | expand10(uz);
        keys[j] = ((unsigned long long)code << 11) | (unsigned)j;
    }
    if (bx == 0) {
        for (int j = tid; j < NN; j += NT) g_rL[0][b * NN + j] = 1.0f;
    } else {
        for (int j = tid; j < MM; j += NT) g_rR[0][b * MM + j] = 1.0f;
        if (tid == 0) out[b] = 0.0f;
    }
    __syncthreads();

    for (int k = 2; k <= NN; k <<= 1) {
        for (int jj = k >> 1; jj > 0; jj >>= 1) {
#pragma unroll 2
            for (int i2 = tid; i2 < NN; i2 += NT) {
                int ixj = i2 ^ jj;
                if (ixj > i2) {
                    bool up = ((i2 & k) == 0);
                    unsigned long long a = keys[i2], c = keys[ixj];
                    if ((a > c) == up) { keys[i2] = c; keys[ixj] = a; }
                }
            }
            __syncthreads();
        }
    }
    for (int j = tid; j < NN; j += NT) {
        int idx = (int)(keys[j] & 2047ull);
        float x = src[idx * 3], y = src[idx * 3 + 1], z = src[idx * 3 + 2];
        dst[j] = make_float4(x, y, z, fmaf(x, x, fmaf(y, y, z * z)));
    }
}

// ---------------- rowsum(level 0): rR==1 -> lg2 term = 0 ----------------
__global__ void __launch_bounds__(NT, 1)
k_rowsum0(float q) {
    __shared__ ulonglong2 tA[MM / 2];   // {pk(n2q*x0,n2q*x1), pk(n2q*y0,n2q*y1)}
    __shared__ ulonglong2 tB[MM / 2];   // {pk(n2q*z0,n2q*z1), pk(q*w0,q*w1)}
    __shared__ float red[NT];
    pdl_trigger();
    const int b = blockIdx.y, bx = blockIdx.x, tid = threadIdx.x;
    const int r  = bx * RPC + (tid & (RPC - 1));
    const int p0 = ((tid >> 7) * SEGL) >> 1;
    const float n2q = -2.0f * q;

    pdl_wait();   // k_sort wrote g_p1/g_p2

    {
        float4 pa = g_p2[b * MM + 2 * tid];
        float4 pb = g_p2[b * MM + 2 * tid + 1];
        tA[tid] = make_ulonglong2(pk2(n2q * pa.x, n2q * pb.x),
                                  pk2(n2q * pa.y, n2q * pb.y));
        tB[tid] = make_ulonglong2(pk2(n2q * pa.z, n2q * pb.z),
                                  pk2(q * pa.w, q * pb.w));
    }
    __syncthreads();

    float4 X = g_p1[b * NN + r];
    u64 Xx = pk2(X.x, X.x), Xy = pk2(X.y, X.y), Xz = pk2(X.z, X.z);
    u64 ap = pk2(q * X.w, q * X.w);

    float s0 = 0.f, s1 = 0.f;
    for (int p = p0; p < p0 + SEGL / 2; p += 2) {
        ulonglong2 A0 = tA[p], B0 = tB[p];
        ulonglong2 A1 = tA[p + 1], B1 = tB[p + 1];
        u64 ta = fmx2(Xx, A0.x, fmx2(Xy, A0.y, fmx2(Xz, B0.x, addx2(ap, B0.y))));
        u64 tb = fmx2(Xx, A1.x, fmx2(Xy, A1.y, fmx2(Xz, B1.x, addx2(ap, B1.y))));
        float t0, t1, t2, t3; upk2(ta, t0, t1); upk2(tb, t2, t3);
        float tm = fmaxf(fmaxf(t0, t1), fmaxf(t2, t3));
        if (__ballot_sync(0xffffffffu, tm > TMIN) != 0u) {
            s0 += ex2f(t0) + ex2f(t2);
            s1 += ex2f(t1) + ex2f(t3);
        }
    }
    red[tid] = s0 + s1;
    __syncthreads();
    if (tid < RPC) {
        float v = 0.f;
#pragma unroll
        for (int k = 0; k < SEGS; k++) v += red[tid + (k << 7)];
        g_s[(size_t)b * NN + bx * RPC + tid] = v;
    }
}

// ---------------- colsum: ss[b][m] ----------------
__global__ void __launch_bounds__(NT, 1)
k_colsum(int cur, float q) {
    __shared__ ulonglong2 tA[NN / 2];
    __shared__ ulonglong2 tB[NN / 2];
    __shared__ float red[NT];
    pdl_trigger();
    const int b = blockIdx.y, bx = blockIdx.x, tid = threadIdx.x;
    const int mcol = bx * RPC + (tid & (RPC - 1));
    const int p0 = ((tid >> 7) * SEGL) >> 1;
    const float n2q = -2.0f * q;

    pdl_wait();   // predecessor wrote g_rL, g_s, g_rR

    {
        float4 pa = g_p1[b * NN + 2 * tid];
        float4 pb = g_p1[b * NN + 2 * tid + 1];
        float rla = g_rL[cur][b * NN + 2 * tid];
        float rlb = g_rL[cur][b * NN + 2 * tid + 1];
        float sva = g_s[b * NN + 2 * tid];
        float svb = g_s[b * NN + 2 * tid + 1];
        float wa = fmaf(q, pa.w, lg2f(__fdividef(rla, sva + EPSF)));
        float wb = fmaf(q, pb.w, lg2f(__fdividef(rlb, svb + EPSF)));
        tA[tid] = make_ulonglong2(pk2(n2q * pa.x, n2q * pb.x),
                                  pk2(n2q * pa.y, n2q * pb.y));
        tB[tid] = make_ulonglong2(pk2(n2q * pa.z, n2q * pb.z), pk2(wa, wb));
    }
    __syncthreads();

    float4 Y = g_p2[b * MM + mcol];
    float c = fmaf(q, Y.w, lg2f(g_rR[cur][b * MM + mcol]));
    u64 Yx = pk2(Y.x, Y.x), Yy = pk2(Y.y, Y.y), Yz = pk2(Y.z, Y.z);
    u64 cp = pk2(c, c);

    float s0 = 0.f, s1 = 0.f;
    for (int p = p0; p < p0 + SEGL / 2; p += 2) {
        ulonglong2 A0 = tA[p], B0 = tB[p];
        ulonglong2 A1 = tA[p + 1], B1 = tB[p + 1];
        u64 ta = fmx2(Yx, A0.x, fmx2(Yy, A0.y, fmx2(Yz, B0.x, addx2(cp, B0.y))));
        u64 tb = fmx2(Yx, A1.x, fmx2(Yy, A1.y, fmx2(Yz, B1.x, addx2(cp, B1.y))));
        float t0, t1, t2, t3; upk2(ta, t0, t1); upk2(tb, t2, t3);
        float tm = fmaxf(fmaxf(t0, t1), fmaxf(t2, t3));
        if (__ballot_sync(0xffffffffu, tm > TMIN) != 0u) {
            s0 += ex2f(t0) + ex2f(t2);
            s1 += ex2f(t1) + ex2f(t3);
        }
    }
    red[tid] = s0 + s1;
    __syncthreads();
    if (tid < RPC) {
        float v = 0.f;
#pragma unroll
        for (int k = 0; k < SEGS; k++) v += red[tid + (k << 7)];
        g_ss[b * MM + bx * RPC + tid] = v;
    }
}

// ---------------- fused: pass3(level i) + rowsum(level i+1) ----------------
// LAST (q2==0): u-stream == rrn, row-independent -> deleted; k_last
// recovers S2 = sum(rrn) itself.
template <bool LAST>
__global__ void __launch_bounds__(NT, 1)
k_fused(int cur, float q, float q2, float* __restrict__ out) {
    __shared__ ulonglong2 tA[MM / 2];   // {pk(-x0,-x1), pk(-y0,-y1)}
    __shared__ ulonglong2 tB[MM / 2];   // {pk(-z0,-z1), pk(lgw0,lgw1)}
    __shared__ u64 t2u[MM / 2];         // pk(lg2(rrn)0, lg2(rrn)1) (unused if LAST)
    __shared__ float red[NT];
    __shared__ float cwarp[NT / 32];
    pdl_trigger();
    const int b = blockIdx.y, bx = blockIdx.x, tid = threadIdx.x;
    const int lane = tid & 31, wid = tid >> 5;
    const int r  = bx * RPC + (tid & (RPC - 1));
    const int p0 = ((tid >> 7) * SEGL) >> 1;
    const int rown = b * NN + bx * RPC + tid;

    pdl_wait();   // predecessor colsum wrote g_ss

    {
        float4 pa = g_p2[b * MM + 2 * tid];
        float4 pb = g_p2[b * MM + 2 * tid + 1];
        float rra = g_rR[cur][b * MM + 2 * tid];
        float rrb = g_rR[cur][b * MM + 2 * tid + 1];
        float ssa = g_ss[b * MM + 2 * tid];
        float ssb = g_ss[b * MM + 2 * tid + 1];
        float raa = fminf(__fdividef(rra, ssa + EPSF), 1.0f);
        float rab = fminf(__fdividef(rrb, ssb + EPSF), 1.0f);
        tA[tid] = make_ulonglong2(pk2(-pa.x, -pb.x), pk2(-pa.y, -pb.y));
        tB[tid] = make_ulonglong2(pk2(-pa.z, -pb.z),
                                  pk2(lg2f(rra * raa), lg2f(rrb * rab)));
        float rrna = fmaxf(rra - raa * ssa, 0.0f);
        float rrnb = fmaxf(rrb - rab * ssb, 0.0f);
        if (!LAST) t2u[tid] = pk2(lg2f(rrna), lg2f(rrnb));
        if (bx == 0) {
            g_rR[cur ^ 1][b * MM + 2 * tid]     = rrna;   // exact identity
            g_rR[cur ^ 1][b * MM + 2 * tid + 1] = rrnb;
        }
    }
    __syncthreads();

    float4 X = g_p1[b * NN + r];
    float rl = g_rL[cur][b * NN + r];
    float sv = g_s[b * NN + r];
    float F  = __fdividef(rl, sv + EPSF);   // hoisted per-row factor
    u64 Xx = pk2(X.x, X.x), Xy = pk2(X.y, X.y), Xz = pk2(X.z, X.z);
    u64 qp = pk2(q, q), q2p = pk2(q2, q2);

    float rs0 = 0.f, rs1 = 0.f, c0 = 0.f, c1 = 0.f, sn0 = 0.f, sn1 = 0.f;
    for (int p = p0; p < p0 + SEGL / 2; p += 2) {
        ulonglong2 A0 = tA[p], B0 = tB[p];
        ulonglong2 A1 = tA[p + 1], B1 = tB[p + 1];
        u64 dxa = addx2(Xx, A0.x);
        u64 dya = addx2(Xy, A0.y);
        u64 dza = addx2(Xz, B0.x);
        u64 d2a = fmx2(dxa, dxa, fmx2(dya, dya, mulx2(dza, dza)));
        u64 dxb = addx2(Xx, A1.x);
        u64 dyb = addx2(Xy, A1.y);
        u64 dzb = addx2(Xz, B1.x);
        u64 d2b = fmx2(dxb, dxb, fmx2(dyb, dyb, mulx2(dzb, dzb)));
        u64 ta = fmx2(d2a, qp, B0.y);
        u64 tb = fmx2(d2b, qp, B1.y);
        float t0, t1, t2, t3; upk2(ta, t0, t1); upk2(tb, t2, t3);
        float d20, d21, d22, d23; upk2(d2a, d20, d21); upk2(d2b, d22, d23);
        float tm = fmaxf(fmaxf(t0, t1), fmaxf(t2, t3));
        if (__ballot_sync(0xffffffffu, tm > TMIN) != 0u) {
            float w0 = ex2f(t0), w1 = ex2f(t1), w2 = ex2f(t2), w3 = ex2f(t3);
            rs0 += w0 + w2; rs1 += w1 + w3;
            c0 = fmaf(w0, sqrt_apx(d20), c0);
            c1 = fmaf(w1, sqrt_apx(d21), c1);
            c0 = fmaf(w2, sqrt_apx(d22), c0);
            c1 = fmaf(w3, sqrt_apx(d23), c1);
        }
        if (!LAST) {
            u64 ua = fmx2(d2a, q2p, t2u[p]);
            u64 ub = fmx2(d2b, q2p, t2u[p + 1]);
            float u0, u1, u2, u3; upk2(ua, u0, u1); upk2(ub, u2, u3);
            float um = fmaxf(fmaxf(u0, u1), fmaxf(u2, u3));
            if (__ballot_sync(0xffffffffu, um > TMIN) != 0u) {
                sn0 += ex2f(u0) + ex2f(u2);
                sn1 += ex2f(u1) + ex2f(u3);
            }
        }
    }

    float c = (c0 + c1) * F;
#pragma unroll
    for (int off = 16; off > 0; off >>= 1)
        c += __shfl_down_sync(0xffffffffu, c, off);
    if (lane == 0) cwarp[wid] = c;

    red[tid] = rs0 + rs1;
    __syncthreads();
    if (tid < RPC) {
        float v = 0.f;
#pragma unroll
        for (int k = 0; k < SEGS; k++) v += red[tid + (k << 7)];
        g_rL[cur ^ 1][rown] = fmaxf(rl - v * F, 0.0f);   // tid<RPC owns row r
    }
    if (!LAST) {
        __syncthreads();
        red[tid] = sn0 + sn1;
        __syncthreads();
        if (tid < RPC) {
            float v = 0.f;
#pragma unroll
            for (int k = 0; k < SEGS; k++) v += red[tid + (k << 7)];
            g_s[rown] = v;                               // rowsum for level i+1
        }
    }
    if (wid == 0) {
        float v = cwarp[lane];
#pragma unroll
        for (int off = 16; off > 0; off >>= 1)
            v += __shfl_down_sync(0xffffffffu, v, off);
        if (lane == 0) atomicAdd(&out[b], v);
    }
}

// ---------------- level 9 (L=0): analytic, single packed cost pass ----------------
__global__ void __launch_bounds__(NT, 1)
k_last(int cur, float* __restrict__ out) {
    __shared__ ulonglong2 tA[MM / 2];   // {pk(-x0,-x1), pk(-y0,-y1)}
    __shared__ ulonglong2 tB[MM / 2];   // {pk(-z0,-z1), pk(w0,w1)} w = rr*ratio
    __shared__ float red[NT];
    __shared__ float cwarp[NT / 32];
    __shared__ float sh2[2];
    pdl_trigger();
    const int b = blockIdx.y, bx = blockIdx.x, tid = threadIdx.x;
    const int lane = tid & 31, wid = tid >> 5;
    const int r  = bx * RPC + (tid & (RPC - 1));
    const int p0 = ((tid >> 7) * SEGL) >> 1;

    pdl_wait();

    const float* rR = g_rR[cur] + b * MM;
    const float* rL = g_rL[cur] + b * NN;

    float aL = 0.f, aR = 0.f;
    for (int j = tid; j < NN; j += NT) { aL += rL[j]; aR += rR[j]; }
    red[tid] = aL;
    __syncthreads();
    if (tid < 32) {
        float v = 0.f;
#pragma unroll
        for (int k = 0; k < NT / 32; k++) v += red[tid + k * 32];
#pragma unroll
        for (int off = 16; off > 0; off >>= 1)
            v += __shfl_down_sync(0xffffffffu, v, off);
        if (tid == 0) sh2[0] = v;
    }
    __syncthreads();
    red[tid] = aR;
    __syncthreads();
    if (tid < 32) {
        float v = 0.f;
#pragma unroll
        for (int k = 0; k < NT / 32; k++) v += red[tid + k * 32];
#pragma unroll
        for (int off = 16; off > 0; off >>= 1)
            v += __shfl_down_sync(0xffffffffu, v, off);
        if (tid == 0) sh2[1] = v;
    }
    __syncthreads();
    const float S2 = sh2[1];
    const float SL = __fdividef(sh2[0], S2 + EPSF);

    {
        float4 pa = g_p2[b * MM + 2 * tid];
        float4 pb = g_p2[b * MM + 2 * tid + 1];
        float rra = rR[2 * tid], rrb = rR[2 * tid + 1];
        float wa = rra * fminf(__fdividef(rra, fmaf(rra, SL, EPSF)), 1.0f);
        float wb = rrb * fminf(__fdividef(rrb, fmaf(rrb, SL, EPSF)), 1.0f);
        tA[tid] = make_ulonglong2(pk2(-pa.x, -pb.x), pk2(-pa.y, -pb.y));
        tB[tid] = make_ulonglong2(pk2(-pa.z, -pb.z), pk2(wa, wb));
    }
    __syncthreads();

    float4 X = g_p1[b * NN + r];
    float F = __fdividef(rL[r], S2 + EPSF);
    u64 Xx = pk2(X.x, X.x), Xy = pk2(X.y, X.y), Xz = pk2(X.z, X.z);

    float c0 = 0.f, c1 = 0.f;
    for (int p = p0; p < p0 + SEGL / 2; p += 2) {
        ulonglong2 A0 = tA[p], B0 = tB[p];
        ulonglong2 A1 = tA[p + 1], B1 = tB[p + 1];
        u64 dxa = addx2(Xx, A0.x);
        u64 dya = addx2(Xy, A0.y);
        u64 dza = addx2(Xz, B0.x);
        u64 d2a = fmx2(dxa, dxa, fmx2(dya, dya, mulx2(dza, dza)));
        u64 dxb = addx2(Xx, A1.x);
        u64 dyb = addx2(Xy, A1.y);
        u64 dzb = addx2(Xz, B1.x);
        u64 d2b = fmx2(dxb, dxb, fmx2(dyb, dyb, mulx2(dzb, dzb)));
        float d20, d21, d22, d23; upk2(d2a, d20, d21); upk2(d2b, d22, d23);
        float w0, w1, w2, w3; upk2(B0.y, w0, w1); upk2(B1.y, w2, w3);
        c0 = fmaf(w0, sqrt_apx(d20), c0);
        c1 = fmaf(w1, sqrt_apx(d21), c1);
        c0 = fmaf(w2, sqrt_apx(d22), c0);
        c1 = fmaf(w3, sqrt_apx(d23), c1);
    }
    float c = (c0 + c1) * F;
#pragma unroll
    for (int off = 16; off > 0; off >>= 1)
        c += __shfl_down_sync(0xffffffffu, c, off);
    if (lane == 0) cwarp[wid] = c;
    __syncthreads();
    if (wid == 0) {
        float v = cwarp[lane];
#pragma unroll
        for (int off = 16; off > 0; off >>= 1)
            v += __shfl_down_sync(0xffffffffu, v, off);
        if (lane == 0) atomicAdd(&out[b], v);
    }
}

extern "C" void kernel_launch(void* const* d_in, const int* in_sizes, int n_in,
                              void* d_out, int out_size) {
    const float* x1 = (const float*)d_in[0];
    const float* x2 = (const float*)d_in[1];
    float* out = (float*)d_out;

    static const float levels[10] = {
        -16384.f, -4096.f, -1024.f, -256.f, -64.f, -16.f, -4.f, -1.f, -0.25f, 0.f
    };

    cudaLaunchConfig_t cfg = {};
    cfg.blockDim = dim3(NT, 1, 1);
    cfg.dynamicSmemBytes = 0;
    cfg.stream = 0;
    cudaLaunchAttribute at;
    at.id = cudaLaunchAttributeProgrammaticStreamSerialization;
    at.val.programmaticStreamSerializationAllowed = 1;

    // sort+init: normal serialization (orders against prior graph replay)
    cfg.gridDim = dim3(2, BB);
    cfg.attrs = nullptr; cfg.numAttrs = 0;
    cudaLaunchKernelEx(&cfg, k_sort, x1, x2, out);

    // rest: PDL-chained
    cfg.gridDim = dim3(NN / RPC, BB);   // (16, 8)
    cfg.attrs = &at; cfg.numAttrs = 1;
    cudaLaunchKernelEx(&cfg, k_rowsum0, levels[0] * LOG2E);

    int cur = 0;
    for (int i = 0; i < 9; i++) {
        float q  = levels[i] * LOG2E;
        float q2 = levels[i + 1] * LOG2E;
        cudaLaunchKernelEx(&cfg, k_colsum, cur, q);
        if (i < 8) cudaLaunchKernelEx(&cfg, k_fused<false>, cur, q, q2, out);
        else       cudaLaunchKernelEx(&cfg, k_fused<true >, cur, q, q2, out);
        cur ^= 1;
    }
    cudaLaunchKernelEx(&cfg, k_last, cur, out);
}

// round 17
// speedup vs baseline: 1.2910x; 1.0672x over previous
#include <cuda_runtime.h>

// EMD approx-match (auction annealing), B=8, N=M=2048, 3-D points.
// R16 = R15 + (1) dot-form t/d2/u in fused (d2 = t/q - lgw/q, u = 0.25*t + T''
// from per-column constants; 12 packed ops -> ~12 but d2/u conditional),
// (2) ballots only at levels i<=3 (they cannot fire at q >= -64),
// (3) dot-form k_last. Clamps: lgw,lgrrn >= -3000 (NaN safety), d2 >= 1e-20.

#define BB 8
#define NN 2048
#define MM 2048
#define EPSF 1e-9f
#define LOG2E 1.4426950408889634f
#define TMIN -126.0f
#define LGMIN -3000.0f

#define NT   1024
#define RPC  128
#define SEGS 8
#define SEGL (MM / SEGS)   // 256 cols = 128 pairs per thread

typedef unsigned long long u64;

__device__ float4 g_p1[BB * NN], g_p2[BB * MM];   // sorted (x,y,z,|p|^2)
__device__ float g_s [BB * NN];
__device__ float g_ss[BB * MM];
__device__ float g_rL[2][BB * NN];
__device__ float g_rR[2][BB * MM];

__device__ __forceinline__ float lg2f(float x) {
    float r; asm("lg2.approx.f32 %0, %1;" : "=f"(r) : "f"(x)); return r;
}
__device__ __forceinline__ float ex2f(float x) {
    float r; asm("ex2.approx.f32 %0, %1;" : "=f"(r) : "f"(x)); return r;
}
__device__ __forceinline__ float sqrt_apx(float x) {
    float r; asm("sqrt.approx.f32 %0, %1;" : "=f"(r) : "f"(x)); return r;
}
__device__ __forceinline__ void pdl_trigger() {
    asm volatile("griddepcontrol.launch_dependents;");
}
__device__ __forceinline__ void pdl_wait() {
    asm volatile("griddepcontrol.wait;" ::: "memory");
}
// ---- packed f32x2 helpers (sm_100+) ----
__device__ __forceinline__ u64 pk2(float a, float b) {
    u64 r; asm("mov.b64 %0, {%1, %2};" : "=l"(r) : "f"(a), "f"(b)); return r;
}
__device__ __forceinline__ void upk2(u64 p, float& a, float& b) {
    asm("mov.b64 {%0, %1}, %2;" : "=f"(a), "=f"(b) : "l"(p));
}
__device__ __forceinline__ u64 addx2(u64 a, u64 b) {
    u64 r; asm("add.rn.f32x2 %0, %1, %2;" : "=l"(r) : "l"(a), "l"(b)); return r;
}
__device__ __forceinline__ u64 fmx2(u64 a, u64 b, u64 c) {
    u64 r; asm("fma.rn.f32x2 %0, %1, %2, %3;" : "=l"(r) : "l"(a), "l"(b), "l"(c)); return r;
}
__device__ __forceinline__ unsigned expand10(unsigned v) {
    v &= 1023u;
    v = (v | (v << 16)) & 0x030000FFu;
    v = (v | (v << 8))  & 0x0300F00Fu;
    v = (v | (v << 4))  & 0x030C30C3u;
    v = (v | (v << 2))  & 0x09249249u;
    return v;
}

// ---------------- Morton sort (one CTA per cloud per batch) + init ----------------
__global__ void __launch_bounds__(NT, 1)
k_sort(const float* __restrict__ x1, const float* __restrict__ x2,
       float* __restrict__ out) {
    __shared__ unsigned long long keys[NN];
    const int b = blockIdx.y, bx = blockIdx.x, tid = threadIdx.x;

    const float* src = (bx == 0) ? x1 + (size_t)b * NN * 3
                                 : x2 + (size_t)b * MM * 3;
    float4* dst = (bx == 0) ? g_p1 + b * NN : g_p2 + b * MM;

    for (int j = tid; j < NN; j += NT) {
        float x = src[j * 3], y = src[j * 3 + 1], z = src[j * 3 + 2];
        unsigned ux = (unsigned)(int)fminf(fmaxf((x + 5.f) * 102.4f, 0.f), 1023.f);
        unsigned uy = (unsigned)(int)fminf(fmaxf((y + 5.f) * 102.4f, 0.f), 1023.f);
        unsigned uz = (unsigned)(int)fminf(fmaxf((z + 5.f) * 102.4f, 0.f), 1023.f);
        unsigned code = (expand10(ux) << 2) | (expand10(uy) << 1) | expand10(uz);
        keys[j] = ((unsigned long long)code << 11) | (unsigned)j;
    }
    if (bx == 0) {
        for (int j = tid; j < NN; j += NT) g_rL[0][b * NN + j] = 1.0f;
    } else {
        for (int j = tid; j < MM; j += NT) g_rR[0][b * MM + j] = 1.0f;
        if (tid == 0) out[b] = 0.0f;
    }
    __syncthreads();

    for (int k = 2; k <= NN; k <<= 1) {
        for (int jj = k >> 1; jj > 0; jj >>= 1) {
#pragma unroll 2
            for (int i2 = tid; i2 < NN; i2 += NT) {
                int ixj = i2 ^ jj;
                if (ixj > i2) {
                    bool up = ((i2 & k) == 0);
                    unsigned long long a = keys[i2], c = keys[ixj];
                    if ((a > c) == up) { keys[i2] = c; keys[ixj] = a; }
                }
            }
            __syncthreads();
        }
    }
    for (int j = tid; j < NN; j += NT) {
        int idx = (int)(keys[j] & 2047ull);
        float x = src[idx * 3], y = src[idx * 3 + 1], z = src[idx * 3 + 2];
        dst[j] = make_float4(x, y, z, fmaf(x, x, fmaf(y, y, z * z)));
    }
}

// ---------------- rowsum(level 0): rR==1 -> lg2 term = 0 ----------------
__global__ void __launch_bounds__(NT, 1)
k_rowsum0(float q) {
    __shared__ ulonglong2 tA[MM / 2];
    __shared__ ulonglong2 tB[MM / 2];
    __shared__ float red[NT];
    pdl_trigger();
    const int b = blockIdx.y, bx = blockIdx.x, tid = threadIdx.x;
    const int r  = bx * RPC + (tid & (RPC - 1));
    const int p0 = ((tid >> 7) * SEGL) >> 1;
    const float n2q = -2.0f * q;

    pdl_wait();   // k_sort wrote g_p1/g_p2

    {
        float4 pa = g_p2[b * MM + 2 * tid];
        float4 pb = g_p2[b * MM + 2 * tid + 1];
        tA[tid] = make_ulonglong2(pk2(n2q * pa.x, n2q * pb.x),
                                  pk2(n2q * pa.y, n2q * pb.y));
        tB[tid] = make_ulonglong2(pk2(n2q * pa.z, n2q * pb.z),
                                  pk2(q * pa.w, q * pb.w));
    }
    __syncthreads();

    float4 X = g_p1[b * NN + r];
    u64 Xx = pk2(X.x, X.x), Xy = pk2(X.y, X.y), Xz = pk2(X.z, X.z);
    u64 ap = pk2(q * X.w, q * X.w);

    float s0 = 0.f, s1 = 0.f;
    for (int p = p0; p < p0 + SEGL / 2; p += 2) {
        ulonglong2 A0 = tA[p], B0 = tB[p];
        ulonglong2 A1 = tA[p + 1], B1 = tB[p + 1];
        u64 ta = fmx2(Xx, A0.x, fmx2(Xy, A0.y, fmx2(Xz, B0.x, addx2(ap, B0.y))));
        u64 tb = fmx2(Xx, A1.x, fmx2(Xy, A1.y, fmx2(Xz, B1.x, addx2(ap, B1.y))));
        float t0, t1, t2, t3; upk2(ta, t0, t1); upk2(tb, t2, t3);
        float tm = fmaxf(fmaxf(t0, t1), fmaxf(t2, t3));
        if (__ballot_sync(0xffffffffu, tm > TMIN) != 0u) {
            s0 += ex2f(t0) + ex2f(t2);
            s1 += ex2f(t1) + ex2f(t3);
        }
    }
    red[tid] = s0 + s1;
    __syncthreads();
    if (tid < RPC) {
        float v = 0.f;
#pragma unroll
        for (int k = 0; k < SEGS; k++) v += red[tid + (k << 7)];
        g_s[(size_t)b * NN + bx * RPC + tid] = v;
    }
}

// ---------------- colsum: ss[b][m] ----------------
template <bool BAL>
__global__ void __launch_bounds__(NT, 1)
k_colsum(int cur, float q) {
    __shared__ ulonglong2 tA[NN / 2];
    __shared__ ulonglong2 tB[NN / 2];
    __shared__ float red[NT];
    pdl_trigger();
    const int b = blockIdx.y, bx = blockIdx.x, tid = threadIdx.x;
    const int mcol = bx * RPC + (tid & (RPC - 1));
    const int p0 = ((tid >> 7) * SEGL) >> 1;
    const float n2q = -2.0f * q;

    pdl_wait();   // predecessor wrote g_rL, g_s, g_rR

    {
        float4 pa = g_p1[b * NN + 2 * tid];
        float4 pb = g_p1[b * NN + 2 * tid + 1];
        float rla = g_rL[cur][b * NN + 2 * tid];
        float rlb = g_rL[cur][b * NN + 2 * tid + 1];
        float sva = g_s[b * NN + 2 * tid];
        float svb = g_s[b * NN + 2 * tid + 1];
        float wa = fmaf(q, pa.w, lg2f(__fdividef(rla, sva + EPSF)));
        float wb = fmaf(q, pb.w, lg2f(__fdividef(rlb, svb + EPSF)));
        tA[tid] = make_ulonglong2(pk2(n2q * pa.x, n2q * pb.x),
                                  pk2(n2q * pa.y, n2q * pb.y));
        tB[tid] = make_ulonglong2(pk2(n2q * pa.z, n2q * pb.z), pk2(wa, wb));
    }
    __syncthreads();

    float4 Y = g_p2[b * MM + mcol];
    float c = fmaf(q, Y.w, lg2f(g_rR[cur][b * MM + mcol]));
    u64 Yx = pk2(Y.x, Y.x), Yy = pk2(Y.y, Y.y), Yz = pk2(Y.z, Y.z);
    u64 cp = pk2(c, c);

    float s0 = 0.f, s1 = 0.f;
    for (int p = p0; p < p0 + SEGL / 2; p += 2) {
        ulonglong2 A0 = tA[p], B0 = tB[p];
        ulonglong2 A1 = tA[p + 1], B1 = tB[p + 1];
        u64 ta = fmx2(Yx, A0.x, fmx2(Yy, A0.y, fmx2(Yz, B0.x, addx2(cp, B0.y))));
        u64 tb = fmx2(Yx, A1.x, fmx2(Yy, A1.y, fmx2(Yz, B1.x, addx2(cp, B1.y))));
        float t0, t1, t2, t3; upk2(ta, t0, t1); upk2(tb, t2, t3);
        bool go = true;
        if (BAL) {
            float tm = fmaxf(fmaxf(t0, t1), fmaxf(t2, t3));
            go = __ballot_sync(0xffffffffu, tm > TMIN) != 0u;
        }
        if (go) {
            s0 += ex2f(t0) + ex2f(t2);
            s1 += ex2f(t1) + ex2f(t3);
        }
    }
    red[tid] = s0 + s1;
    __syncthreads();
    if (tid < RPC) {
        float v = 0.f;
#pragma unroll
        for (int k = 0; k < SEGS; k++) v += red[tid + (k << 7)];
        g_ss[b * MM + bx * RPC + tid] = v;
    }
}

// ---------------- fused: pass3(level i) + rowsum(level i+1) ----------------
// MODE: 0 = SPARSE (ballots), 1 = DENSE (no ballots), 2 = LAST (no u-stream).
// Dot-form: t = q|x|^2 + x.(-2q y) + (q|y|^2 + lgw);  d2 = t*invq - lgw*invq;
//           u = kq*t + (lgrrn - kq*lgw),  kq = q2/q (= 0.25 for all levels).
template <int MODE>
__global__ void __launch_bounds__(NT, 1)
k_fused(int cur, float q, float invq, float kq, float* __restrict__ out) {
    extern __shared__ char sm[];
    ulonglong2* tA = (ulonglong2*)(sm);            // {pk(-2q x),pk(-2q y)}   16K
    ulonglong2* tB = (ulonglong2*)(sm + 16384);    // {pk(-2q z),pk(w')}      16K
    ulonglong2* tC = (ulonglong2*)(sm + 32768);    // {pk(-lgw/q),pk(T'')}    16K
    float* red   = (float*)(sm + 49152);           // 4K
    float* cwarp = (float*)(sm + 53248);
    pdl_trigger();
    const int b = blockIdx.y, bx = blockIdx.x, tid = threadIdx.x;
    const int lane = tid & 31, wid = tid >> 5;
    const int r  = bx * RPC + (tid & (RPC - 1));
    const int p0 = ((tid >> 7) * SEGL) >> 1;
    const int rown = b * NN + bx * RPC + tid;
    const float n2q = -2.0f * q;

    pdl_wait();   // predecessor colsum wrote g_ss

    {
        float4 pa = g_p2[b * MM + 2 * tid];
        float4 pb = g_p2[b * MM + 2 * tid + 1];
        float rra = g_rR[cur][b * MM + 2 * tid];
        float rrb = g_rR[cur][b * MM + 2 * tid + 1];
        float ssa = g_ss[b * MM + 2 * tid];
        float ssb = g_ss[b * MM + 2 * tid + 1];
        float raa = fminf(__fdividef(rra, ssa + EPSF), 1.0f);
        float rab = fminf(__fdividef(rrb, ssb + EPSF), 1.0f);
        float lgwa = fmaxf(lg2f(rra * raa), LGMIN);
        float lgwb = fmaxf(lg2f(rrb * rab), LGMIN);
        tA[tid] = make_ulonglong2(pk2(n2q * pa.x, n2q * pb.x),
                                  pk2(n2q * pa.y, n2q * pb.y));
        tB[tid] = make_ulonglong2(pk2(n2q * pa.z, n2q * pb.z),
                                  pk2(fmaf(q, pa.w, lgwa), fmaf(q, pb.w, lgwb)));
        float rrna = fmaxf(rra - raa * ssa, 0.0f);
        float rrnb = fmaxf(rrb - rab * ssb, 0.0f);
        if (MODE != 2) {
            float lgra = fmaxf(lg2f(rrna), LGMIN);
            float lgrb = fmaxf(lg2f(rrnb), LGMIN);
            tC[tid] = make_ulonglong2(pk2(-lgwa * invq, -lgwb * invq),
                                      pk2(fmaf(-kq, lgwa, lgra),
                                          fmaf(-kq, lgwb, lgrb)));
        } else {
            tC[tid] = make_ulonglong2(pk2(-lgwa * invq, -lgwb * invq), 0ull);
        }
        if (bx == 0) {
            g_rR[cur ^ 1][b * MM + 2 * tid]     = rrna;   // exact identity
            g_rR[cur ^ 1][b * MM + 2 * tid + 1] = rrnb;
        }
    }
    __syncthreads();

    float4 X = g_p1[b * NN + r];
    float rl = g_rL[cur][b * NN + r];
    float sv = g_s[b * NN + r];
    float F  = __fdividef(rl, sv + EPSF);   // hoisted per-row factor
    u64 Xx = pk2(X.x, X.x), Xy = pk2(X.y, X.y), Xz = pk2(X.z, X.z);
    u64 ap = pk2(q * X.w, q * X.w);
    u64 invqp = pk2(invq, invq), kqp = pk2(kq, kq);

    float rs0 = 0.f, rs1 = 0.f, c0 = 0.f, c1 = 0.f, sn0 = 0.f, sn1 = 0.f;
    for (int p = p0; p < p0 + SEGL / 2; p += 2) {
        ulonglong2 A0 = tA[p], B0 = tB[p];
        ulonglong2 A1 = tA[p + 1], B1 = tB[p + 1];
        u64 ta = fmx2(Xx, A0.x, fmx2(Xy, A0.y, fmx2(Xz, B0.x, addx2(ap, B0.y))));
        u64 tb = fmx2(Xx, A1.x, fmx2(Xy, A1.y, fmx2(Xz, B1.x, addx2(ap, B1.y))));
        ulonglong2 C0 = tC[p], C1 = tC[p + 1];
        float t0, t1, t2, t3; upk2(ta, t0, t1); upk2(tb, t2, t3);
        bool alive = true;
        if (MODE == 0) {
            float tm = fmaxf(fmaxf(t0, t1), fmaxf(t2, t3));
            alive = __ballot_sync(0xffffffffu, tm > TMIN) != 0u;
        }
        if (alive) {
            u64 d2a = fmx2(ta, invqp, C0.x);
            u64 d2b = fmx2(tb, invqp, C1.x);
            float d20, d21, d22, d23; upk2(d2a, d20, d21); upk2(d2b, d22, d23);
            d20 = fmaxf(d20, 1e-20f); d21 = fmaxf(d21, 1e-20f);
            d22 = fmaxf(d22, 1e-20f); d23 = fmaxf(d23, 1e-20f);
            float w0 = ex2f(t0), w1 = ex2f(t1), w2 = ex2f(t2), w3 = ex2f(t3);
            rs0 += w0 + w2; rs1 += w1 + w3;
            c0 = fmaf(w0, sqrt_apx(d20), c0);
            c1 = fmaf(w1, sqrt_apx(d21), c1);
            c0 = fmaf(w2, sqrt_apx(d22), c0);
            c1 = fmaf(w3, sqrt_apx(d23), c1);
        }
        if (MODE != 2) {
            u64 ua = fmx2(ta, kqp, C0.y);
            u64 ub = fmx2(tb, kqp, C1.y);
            float u0, u1, u2, u3; upk2(ua, u0, u1); upk2(ub, u2, u3);
            bool go2 = true;
            if (MODE == 0) {
                float um = fmaxf(fmaxf(u0, u1), fmaxf(u2, u3));
                go2 = __ballot_sync(0xffffffffu, um > TMIN) != 0u;
            }
            if (go2) {
                sn0 += ex2f(u0) + ex2f(u2);
                sn1 += ex2f(u1) + ex2f(u3);
            }
        }
    }

    float c = (c0 + c1) * F;
#pragma unroll
    for (int off = 16; off > 0; off >>= 1)
        c += __shfl_down_sync(0xffffffffu, c, off);
    if (lane == 0) cwarp[wid] = c;

    red[tid] = rs0 + rs1;
    __syncthreads();
    if (tid < RPC) {
        float v = 0.f;
#pragma unroll
        for (int k = 0; k < SEGS; k++) v += red[tid + (k << 7)];
        g_rL[cur ^ 1][rown] = fmaxf(rl - v * F, 0.0f);   // tid<RPC owns row r
    }
    if (MODE != 2) {
        __syncthreads();
        red[tid] = sn0 + sn1;
        __syncthreads();
        if (tid < RPC) {
            float v = 0.f;
#pragma unroll
            for (int k = 0; k < SEGS; k++) v += red[tid + (k << 7)];
            g_s[rown] = v;                               // rowsum for level i+1
        }
    }
    if (wid == 0) {
        float v = cwarp[lane];
#pragma unroll
        for (int off = 16; off > 0; off >>= 1)
            v += __shfl_down_sync(0xffffffffu, v, off);
        if (lane == 0) atomicAdd(&out[b], v);
    }
}

// ---------------- level 9 (L=0): analytic, dot-form packed cost pass ----------------
__global__ void __launch_bounds__(NT, 1)
k_last(int cur, float* __restrict__ out) {
    __shared__ ulonglong2 tA[MM / 2];   // {pk(-2y_x), pk(-2y_y)}
    __shared__ ulonglong2 tB[MM / 2];   // {pk(-2y_z), pk(|y|^2)}
    __shared__ u64 tW[MM / 2];          // pk(w0,w1), w = rr*ratio
    __shared__ float red[NT];
    __shared__ float cwarp[NT / 32];
    __shared__ float sh2[2];
    pdl_trigger();
    const int b = blockIdx.y, bx = blockIdx.x, tid = threadIdx.x;
    const int lane = tid & 31, wid = tid >> 5;
    const int r  = bx * RPC + (tid & (RPC - 1));
    const int p0 = ((tid >> 7) * SEGL) >> 1;

    pdl_wait();

    const float* rR = g_rR[cur] + b * MM;
    const float* rL = g_rL[cur] + b * NN;

    float aL = 0.f, aR = 0.f;
    for (int j = tid; j < NN; j += NT) { aL += rL[j]; aR += rR[j]; }
    red[tid] = aL;
    __syncthreads();
    if (tid < 32) {
        float v = 0.f;
#pragma unroll
        for (int k = 0; k < NT / 32; k++) v += red[tid + k * 32];
#pragma unroll
        for (int off = 16; off > 0; off >>= 1)
            v += __shfl_down_sync(0xffffffffu, v, off);
        if (tid == 0) sh2[0] = v;
    }
    __syncthreads();
    red[tid] = aR;
    __syncthreads();
    if (tid < 32) {
        float v = 0.f;
#pragma unroll
        for (int k = 0; k < NT / 32; k++) v += red[tid + k * 32];
#pragma unroll
        for (int off = 16; off > 0; off >>= 1)
            v += __shfl_down_sync(0xffffffffu, v, off);
        if (tid == 0) sh2[1] = v;
    }
    __syncthreads();
    const float S2 = sh2[1];
    const float SL = __fdividef(sh2[0], S2 + EPSF);

    {
        float4 pa = g_p2[b * MM + 2 * tid];
        float4 pb = g_p2[b * MM + 2 * tid + 1];
        float rra = rR[2 * tid], rrb = rR[2 * tid + 1];
        float wa = rra * fminf(__fdividef(rra, fmaf(rra, SL, EPSF)), 1.0f);
        float wb = rrb * fminf(__fdividef(rrb, fmaf(rrb, SL, EPSF)), 1.0f);
        tA[tid] = make_ulonglong2(pk2(-2.f * pa.x, -2.f * pb.x),
                                  pk2(-2.f * pa.y, -2.f * pb.y));
        tB[tid] = make_ulonglong2(pk2(-2.f * pa.z, -2.f * pb.z),
                                  pk2(pa.w, pb.w));
        tW[tid] = pk2(wa, wb);
    }
    __syncthreads();

    float4 X = g_p1[b * NN + r];
    float F = __fdividef(rL[r], S2 + EPSF);
    u64 Xx = pk2(X.x, X.x), Xy = pk2(X.y, X.y), Xz = pk2(X.z, X.z);
    u64 ap = pk2(X.w, X.w);

    float c0 = 0.f, c1 = 0.f;
    for (int p = p0; p < p0 + SEGL / 2; p += 2) {
        ulonglong2 A0 = tA[p], B0 = tB[p];
        ulonglong2 A1 = tA[p + 1], B1 = tB[p + 1];
        u64 d2a = fmx2(Xx, A0.x, fmx2(Xy, A0.y, fmx2(Xz, B0.x, addx2(ap, B0.y))));
        u64 d2b = fmx2(Xx, A1.x, fmx2(Xy, A1.y, fmx2(Xz, B1.x, addx2(ap, B1.y))));
        float d20, d21, d22, d23; upk2(d2a, d20, d21); upk2(d2b, d22, d23);
        d20 = fmaxf(d20, 1e-20f); d21 = fmaxf(d21, 1e-20f);
        d22 = fmaxf(d22, 1e-20f); d23 = fmaxf(d23, 1e-20f);
        float w0, w1, w2, w3; upk2(tW[p], w0, w1); upk2(tW[p + 1], w2, w3);
        c0 = fmaf(w0, sqrt_apx(d20), c0);
        c1 = fmaf(w1, sqrt_apx(d21), c1);
        c0 = fmaf(w2, sqrt_apx(d22), c0);
        c1 = fmaf(w3, sqrt_apx(d23), c1);
    }
    float c = (c0 + c1) * F;
#pragma unroll
    for (int off = 16; off > 0; off >>= 1)
        c += __shfl_down_sync(0xffffffffu, c, off);
    if (lane == 0) cwarp[wid] = c;
    __syncthreads();
    if (wid == 0) {
        float v = cwarp[lane];
#pragma unroll
        for (int off = 16; off > 0; off >>= 1)
            v += __shfl_down_sync(0xffffffffu, v, off);
        if (lane == 0) atomicAdd(&out[b], v);
    }
}

#define FUSED_SMEM 53376

extern "C" void kernel_launch(void* const* d_in, const int* in_sizes, int n_in,
                              void* d_out, int out_size) {
    const float* x1 = (const float*)d_in[0];
    const float* x2 = (const float*)d_in[1];
    float* out = (float*)d_out;

    static const float levels[10] = {
        -16384.f, -4096.f, -1024.f, -256.f, -64.f, -16.f, -4.f, -1.f, -0.25f, 0.f
    };

    cudaFuncSetAttribute(k_fused<0>, cudaFuncAttributeMaxDynamicSharedMemorySize, FUSED_SMEM);
    cudaFuncSetAttribute(k_fused<1>, cudaFuncAttributeMaxDynamicSharedMemorySize, FUSED_SMEM);
    cudaFuncSetAttribute(k_fused<2>, cudaFuncAttributeMaxDynamicSharedMemorySize, FUSED_SMEM);

    cudaLaunchConfig_t cfg = {};
    cfg.blockDim = dim3(NT, 1, 1);
    cfg.dynamicSmemBytes = 0;
    cfg.stream = 0;
    cudaLaunchAttribute at;
    at.id = cudaLaunchAttributeProgrammaticStreamSerialization;
    at.val.programmaticStreamSerializationAllowed = 1;

    // sort+init: normal serialization (orders against prior graph replay)
    cfg.gridDim = dim3(2, BB);
    cfg.attrs = nullptr; cfg.numAttrs = 0;
    cudaLaunchKernelEx(&cfg, k_sort, x1, x2, out);

    // rest: PDL-chained
    cfg.gridDim = dim3(NN / RPC, BB);   // (16, 8)
    cfg.attrs = &at; cfg.numAttrs = 1;
    cudaLaunchKernelEx(&cfg, k_rowsum0, levels[0] * LOG2E);

    int cur = 0;
    for (int i = 0; i < 9; i++) {
        float q   = levels[i] * LOG2E;
        float inq = 1.0f / q;
        float kq  = levels[i + 1] / levels[i];   // 0.25 exactly (0 unused at i=8)

        cfg.dynamicSmemBytes = 0;
        if (i <= 3) cudaLaunchKernelEx(&cfg, k_colsum<true >, cur, q);
        else        cudaLaunchKernelEx(&cfg, k_colsum<false>, cur, q);

        cfg.dynamicSmemBytes = FUSED_SMEM;
        if (i <= 3)      cudaLaunchKernelEx(&cfg, k_fused<0>, cur, q, inq, kq, out);
        else if (i <= 7) cudaLaunchKernelEx(&cfg, k_fused<1>, cur, q, inq, kq, out);
        else             cudaLaunchKernelEx(&cfg, k_fused<2>, cur, q, inq, 0.f, out);
        cur ^= 1;
    }
    cfg.dynamicSmemBytes = 0;
    cudaLaunchKernelEx(&cfg, k_last, cur, out);
}